// round 6
// baseline (speedup 1.0000x reference)
#include <cuda_runtime.h>
#include <cstdint>

// Problem constants (upper bounds; runtime shapes read from in_sizes)
#define NMAX 16384
#define PMAX 4096
#define NB   65536              // rank buckets for the ranking pipeline
#define RMAX (NMAX + PMAX)      // 20480 distinct ranks max
#define BMW  (RMAX / 32)        // 640 bitmap words
#define SBW  (BMW / 32)         // 20 summary words
#define OVF_CAP 128

typedef unsigned long long u64;
typedef unsigned int u32;
typedef unsigned short u16;

// -------- cross-kernel scratch (allocation-free: __device__ globals) --------
__device__ u16 g_writer[PMAX];        // last writer item per slot, 0xFFFF = keep original

__device__ u32 g_hist[NB];            // bucket histogram
__device__ u32 g_prefix[NB];          // exclusive prefix of hist
__device__ u32 g_cursor[NB];          // scatter cursors (init = prefix)
__device__ u32 g_bdata[RMAX];         // ordered-key values grouped by bucket
__device__ u16 g_rank_scores[NMAX];   // exact rank of each score
__device__ u16 g_rank_prior[PMAX];    // exact rank of each input priority

// order-preserving u32 transform of float (total order matching IEEE <)
__device__ __forceinline__ u32 okey(float v) {
    u32 b = __float_as_uint(v);
    return (b & 0x80000000u) ? ~b : (b | 0x80000000u);
}
// monotone bucketing (exactness NOT required; monotone + equal-on-equal is)
__device__ __forceinline__ int bucketOf(float v) {
    if (!(v > 0.0f)) return 0;
    if (v >= 1.0f)   return NB - 1;
    int b = (int)(v * 65536.0f);
    return b < 0 ? 0 : (b > NB - 1 ? NB - 1 : b);
}

// ---------------------------------------------------------------------------
// Rank pipeline: hist -> scan -> scatter -> per-value rank
// rank(v) = #{candidate u : u < v}, candidates = scores[0..N) ∪ priorities[0..P)
// ---------------------------------------------------------------------------
__global__ void k_zero() {
    int i = blockIdx.x * blockDim.x + threadIdx.x;
    if (i < NB) g_hist[i] = 0u;
}

__global__ void k_hist(const float* __restrict__ scores,
                       const float* __restrict__ priorities, int N, int P) {
    int i = blockIdx.x * blockDim.x + threadIdx.x;
    if (i >= N + P) return;
    float v = (i < N) ? scores[i] : priorities[i - N];
    atomicAdd(&g_hist[bucketOf(v)], 1u);
}

__global__ __launch_bounds__(1024, 1) void k_scan() {
    __shared__ u32 wsum[32];
    const int tid = threadIdx.x;
    const int CPT = NB / 1024;            // 64 per thread
    const int base = tid * CPT;
    u32 s = 0;
    #pragma unroll 8
    for (int j = 0; j < CPT; ++j) s += g_hist[base + j];

    const int lane = tid & 31, wid = tid >> 5;
    u32 v = s;
    #pragma unroll
    for (int o = 1; o < 32; o <<= 1) {
        u32 t = __shfl_up_sync(0xFFFFFFFFu, v, o);
        if (lane >= o) v += t;
    }
    if (lane == 31) wsum[wid] = v;
    __syncthreads();
    if (wid == 0) {
        u32 w = wsum[lane];
        #pragma unroll
        for (int o = 1; o < 32; o <<= 1) {
            u32 t = __shfl_up_sync(0xFFFFFFFFu, w, o);
            if (lane >= o) w += t;
        }
        wsum[lane] = w;
    }
    __syncthreads();
    u32 run = (v - s) + ((wid > 0) ? wsum[wid - 1] : 0u);
    #pragma unroll 8
    for (int j = 0; j < CPT; ++j) {
        u32 h = g_hist[base + j];
        g_prefix[base + j] = run;
        g_cursor[base + j] = run;
        run += h;
    }
}

__global__ void k_scatter(const float* __restrict__ scores,
                          const float* __restrict__ priorities, int N, int P) {
    int i = blockIdx.x * blockDim.x + threadIdx.x;
    if (i >= N + P) return;
    float v = (i < N) ? scores[i] : priorities[i - N];
    u32 pos = atomicAdd(&g_cursor[bucketOf(v)], 1u);
    g_bdata[pos] = okey(v);
}

__global__ void k_rank(const float* __restrict__ scores,
                       const float* __restrict__ priorities, int N, int P) {
    int i = blockIdx.x * blockDim.x + threadIdx.x;
    if (i >= N + P) return;
    float v = (i < N) ? scores[i] : priorities[i - N];
    u16 r;
    if (!(v > 0.0f)) {
        r = 0;   // no negative candidates exist -> rank(<=0) = 0 (avoids scanning the big zero bucket)
    } else {
        int b = bucketOf(v);
        u32 k = okey(v);
        u32 base = g_prefix[b];
        u32 n = g_hist[b];
        u32 c = 0;
        for (u32 j = 0; j < n; ++j) c += (g_bdata[base + j] < k) ? 1u : 0u;
        r = (u16)(base + c);   // < N+P = 20480 < 2^15
    }
    if (i < N) g_rank_scores[i] = r; else g_rank_prior[i - N] = r;
}

// ---------------------------------------------------------------------------
// k_sim: classify + exact sequential replace-phase, all in one block.
//
// Pool keys: key = (rank << 12) | slot; lexicographic u32 min == argmin with
// first-index tie-break. The pool lives in a MONOTONE BUCKET QUEUE over ranks:
//   mslot[r] : min slot among live pool entries at rank r
//   bm/sbm   : presence bitmaps (rank -> bit), 2-level
//   ovf[]    : extra same-rank entries (exact duplicate-float ties; tiny)
// Pool-min rank is non-decreasing, so pop-min only ever scans FORWARD.
// Phase-2 stream packed e = (rank << 14) | item; accept iff e >= th where
// th = (poolMinRank + 1) << 14  (<=> rank > poolMinRank <=> score > min).
// ---------------------------------------------------------------------------
__global__ __launch_bounds__(1024, 1)
void k_sim(const float* __restrict__ scores,
           const float* __restrict__ priorities,
           const int* __restrict__ countp,
           float* __restrict__ out,
           int N, int P, int D, long long out_size) {
    extern __shared__ u32 S[];
    float* sc   = (float*)S;            // NMAX staged scores
    u32*  pe    = S + NMAX;             // NMAX+8 packed phase-2 stream (16B aligned)
    u32*  mslot = pe + (NMAX + 8);      // RMAX
    u32*  bm    = mslot + RMAX;         // BMW
    u32*  sbm   = bm + BMW;             // SBW
    u32*  ovf   = sbm + SBW;            // OVF_CAP
    int*  ovfn  = (int*)(ovf + OVF_CAP);// 1 (+3 pad)
    u16*  wr    = (u16*)(ovfn + 4);     // PMAX writer map
    __shared__ int wsum[32];

    const int tid = threadIdx.x;
    const int nthr = blockDim.x;

    // ---- init (coalesced) ----
    for (int i = tid; i < NMAX; i += nthr) sc[i] = (i < N) ? scores[i] : 0.0f;
    for (int i = tid; i < RMAX; i += nthr) mslot[i] = 0xFFFFFFFFu;
    for (int i = tid; i < BMW; i += nthr) bm[i] = 0u;
    if (tid < SBW) sbm[tid] = 0u;
    if (tid == 0) *ovfn = 0;
    for (int i = tid; i < PMAX; i += nthr) wr[i] = 0xFFFFu;
    __syncthreads();

    // ---- classify: prefix-scan of valid flags over smem-staged scores ----
    const int C0 = *countp;
    const int ipt = (N + nthr - 1) / nthr;
    const int start = tid * ipt;
    const int end = min(start + ipt, N);
    int c = 0;
    for (int i = start; i < end; ++i) c += (sc[i] > 0.5f) ? 1 : 0;

    const int lane = tid & 31, wid = tid >> 5;
    int v = c;
    #pragma unroll
    for (int o = 1; o < 32; o <<= 1) {
        int t = __shfl_up_sync(0xFFFFFFFFu, v, o);
        if (lane >= o) v += t;
    }
    if (lane == 31) wsum[wid] = v;
    __syncthreads();
    if (wid == 0) {
        int w = wsum[lane];
        #pragma unroll
        for (int o = 1; o < 32; o <<= 1) {
            int t = __shfl_up_sync(0xFFFFFFFFu, w, o);
            if (lane >= o) w += t;
        }
        wsum[lane] = w;
    }
    __syncthreads();

    const int excl = (v - c) + ((wid > 0) ? wsum[wid - 1] : 0);
    const int total = wsum[(nthr >> 5) - 1];
    int room = P - C0; if (room < 0) room = 0;
    const int T  = (total > room) ? total - room : 0;
    const int fc = C0 + ((total < room) ? total : room);

    int r = excl;
    for (int i = start; i < end; ++i) {
        if (sc[i] > 0.5f) {
            if (r < room) wr[C0 + r] = (u16)i;
            else          pe[r - room] = (u32)i;   // item only; rank tagged below
            r++;
        }
    }
    __syncthreads();

    // ---- tag phase-2 stream with ranks (coalesced; items increase with q) ----
    const int Tpad = (T + 7) & ~7;
    for (int q = tid; q < Tpad; q += nthr) {
        u32 e = 0u;   // padding: e=0 < th (th >= 1<<14) -> always skipped
        if (q < T) {
            u32 it = pe[q];
            e = ((u32)g_rank_scores[it] << 14) | it;
        }
        pe[q] = e;
    }

    // ---- parallel bucket-queue build over live pool keys (only when full) ----
    if (T > 0) {
        for (int i = tid; i < P; i += nthr) {
            u16 w = wr[i];
            u32 rk = (w != 0xFFFFu) ? (u32)g_rank_scores[w] : (u32)g_rank_prior[i];
            atomicMin(&mslot[rk], (u32)i);
            atomicOr(&bm[rk >> 5], 1u << (rk & 31));
            atomicOr(&sbm[rk >> 10], 1u << ((rk >> 5) & 31));
        }
    }
    __syncthreads();
    if (T > 0) {
        for (int i = tid; i < P; i += nthr) {
            u16 w = wr[i];
            u32 rk = (w != 0xFFFFu) ? (u32)g_rank_scores[w] : (u32)g_rank_prior[i];
            if (mslot[rk] != (u32)i) {                  // same-rank tie loser
                int k = atomicAdd(ovfn, 1);
                if (k < OVF_CAP) ovf[k] = (rk << 12) | (u32)i;
            }
        }
    }
    __syncthreads();

    // ---- serial simulation (thread 0) ----
    if (tid == 0 && T > 0) {
        int ovfN = *ovfn; if (ovfN > OVF_CAP) ovfN = OVF_CAP;

        // initial pool min
        u32 insMin;
        {
            int sw = 0; u32 s = sbm[0];
            while (s == 0u) s = sbm[++sw];
            int w = (sw << 5) + (__ffs(s) - 1);
            u32 m = bm[w];
            u32 rr = (u32)((w << 5) + (__ffs(m) - 1));
            insMin = (rr << 12) | mslot[rr];
        }
        u32 th = ((insMin >> 12) + 1u) << 14;

        const uint4* pe4 = (const uint4*)pe;
        for (int q0 = 0; q0 < Tpad; q0 += 8) {
            uint4 A = pe4[q0 >> 2];
            uint4 B = pe4[(q0 >> 2) + 1];
            u32 mx = max(max(max(A.x, A.y), max(A.z, A.w)),
                         max(max(B.x, B.y), max(B.z, B.w)));
            if (mx < th) continue;   // threshold only rises -> conservative skip OK
            u32 ev[8] = {A.x, A.y, A.z, A.w, B.x, B.y, B.z, B.w};
            #pragma unroll
            for (int k = 0; k < 8; ++k) {
                u32 e = ev[k];
                if (e < th) continue;

                // evict current min, write new item at its slot
                u32 slot = insMin & 0xFFFu;
                wr[slot] = (u16)(e & 0x3FFFu);
                u32 nk = ((e >> 14) << 12) | slot;
                u32 rr = insMin >> 12;

                // pop min from bucket queue
                bool promoted = false;
                if (ovfN) {   // rare: same-rank duplicates pending
                    u32 best = 0xFFFFFFFFu; int bi = -1;
                    for (int j = 0; j < ovfN; ++j) {
                        u32 o = ovf[j];
                        if ((o >> 12) == rr && o < best) { best = o; bi = j; }
                    }
                    if (bi >= 0) {
                        ovf[bi] = ovf[ovfN - 1]; ovfN--;
                        mslot[rr] = best & 0xFFFu;
                        insMin = best;
                        promoted = true;
                    }
                }
                if (!promoted) {
                    int w = rr >> 5;
                    u32 nw = bm[w] & ~(1u << (rr & 31));
                    bm[w] = nw;
                    if (nw == 0u) sbm[w >> 5] &= ~(1u << (w & 31));
                    u32 m = nw & (0xFFFFFFFEu << (rr & 31));  // bits strictly above rr
                    if (m == 0u) {
                        int sw = w >> 5;
                        u32 s = sbm[sw] & (0xFFFFFFFEu << (w & 31));
                        while (s == 0u) s = sbm[++sw];        // pool nonempty
                        w = (sw << 5) + (__ffs(s) - 1);
                        m = bm[w];
                    }
                    u32 r2 = (u32)((w << 5) + (__ffs(m) - 1));
                    insMin = (r2 << 12) | mslot[r2];
                }

                // insert new key
                u32 nr = nk >> 12;
                int wq = nr >> 5;
                u32 bw = bm[wq];
                u32 bit = 1u << (nr & 31);
                if (bw & bit) {           // rank occupied -> tie handling
                    u32 ex = (nr << 12) | mslot[nr];
                    if (nk < ex) { mslot[nr] = nk & 0xFFFu; if (ovfN < OVF_CAP) ovf[ovfN++] = ex; }
                    else         { if (ovfN < OVF_CAP) ovf[ovfN++] = nk; }
                } else {
                    bm[wq] = bw | bit;
                    sbm[wq >> 5] |= 1u << (wq & 31);
                    mslot[nr] = nk & 0xFFFu;
                }
                insMin = min(insMin, nk);
                th = ((insMin >> 12) + 1u) << 14;
            }
        }
    }
    __syncthreads();

    // ---- epilogue: writer map to global; priorities + count to output tail ----
    const long long base = (long long)P * (long long)D;
    for (int i = tid; i < P; i += nthr) {
        u16 w = wr[i];
        g_writer[i] = w;
        if (base + i < out_size)
            out[base + i] = (w != 0xFFFFu) ? sc[w] : priorities[i];
    }
    if (tid == 0 && base + P < out_size)
        out[base + P] = (float)fc;
}

// ---------------------------------------------------------------------------
// Row gather: one block per pool slot, copy original pool row or last-writing
// summary row into the output.
// ---------------------------------------------------------------------------
__global__ void k_copy(const float* __restrict__ pool,
                       const float* __restrict__ summaries,
                       float* __restrict__ out, int D) {
    const int row = blockIdx.x;
    const u16 w = g_writer[row];
    const float* src = (w == 0xFFFFu) ? (pool + (long long)row * D)
                                      : (summaries + (long long)w * D);
    float* dst = out + (long long)row * D;
    if ((D & 3) == 0) {
        const float4* s4 = (const float4*)src;
        float4* d4 = (float4*)dst;
        for (int i = threadIdx.x; i < (D >> 2); i += blockDim.x) d4[i] = s4[i];
    } else {
        for (int i = threadIdx.x; i < D; i += blockDim.x) dst[i] = src[i];
    }
}

// ---------------------------------------------------------------------------
// Inputs (metadata order): summaries[N,D] f32, scores[N] f32, pool[P,D] f32,
// priorities[P] f32, count i32 scalar.
// Output: concat(pool_out[P*D], priorities[P], count) as f32.
// ---------------------------------------------------------------------------
extern "C" void kernel_launch(void* const* d_in, const int* in_sizes, int n_in,
                              void* d_out, int out_size) {
    const float* summaries  = (const float*)d_in[0];
    const float* scores     = (const float*)d_in[1];
    const float* pool       = (const float*)d_in[2];
    const float* priorities = (const float*)d_in[3];
    const int*   countp     = (const int*)d_in[4];

    const int N = in_sizes[1];
    const int P = in_sizes[3];
    const int D = (N > 0) ? (in_sizes[0] / N) : 0;
    const int M = N + P;
    float* out = (float*)d_out;

    // smem: sc 64KB + pe 64KB + mslot 80KB + bitmaps ~2.7KB + ovf + wr 8KB
    const int sim_smem = (NMAX + (NMAX + 8) + RMAX + BMW + SBW + OVF_CAP + 4) * 4
                       + PMAX * 2;   // 224384 bytes
    cudaFuncSetAttribute(k_sim, cudaFuncAttributeMaxDynamicSharedMemorySize, sim_smem);

    k_zero   <<<NB / 256, 256>>>();
    k_hist   <<<(M + 255) / 256, 256>>>(scores, priorities, N, P);
    k_scan   <<<1, 1024>>>();
    k_scatter<<<(M + 255) / 256, 256>>>(scores, priorities, N, P);
    k_rank   <<<(M + 255) / 256, 256>>>(scores, priorities, N, P);
    k_sim    <<<1, 1024, sim_smem>>>(scores, priorities, countp, out,
                                     N, P, D, (long long)out_size);
    k_copy   <<<P, 256>>>(pool, summaries, out, D);
}

// round 7
// speedup vs baseline: 1.0356x; 1.0356x over previous
#include <cuda_runtime.h>
#include <cstdint>

// Problem constants (upper bounds; runtime shapes read from in_sizes)
#define NMAX 16384
#define PMAX 4096
#define NB   65536              // rank buckets for the ranking pipeline
#define RMAX (NMAX + PMAX)      // 20480 distinct ranks max
#define BMW  (RMAX / 32)        // 640 bitmap words
#define OVF_CAP 512

typedef unsigned long long u64;
typedef unsigned int u32;
typedef unsigned short u16;

// -------- cross-kernel scratch (allocation-free: __device__ globals) --------
__device__ u16 g_writer[PMAX];        // last writer item per slot, 0xFFFF = keep original

__device__ u32 g_hist[NB];            // bucket histogram
__device__ u32 g_prefix[NB];          // exclusive prefix of hist
__device__ u32 g_cursor[NB];          // scatter cursors (init = prefix)
__device__ u32 g_bdata[RMAX];         // ordered-key values grouped by bucket
__device__ u16 g_rank_scores[NMAX];   // exact rank of each score
__device__ u16 g_rank_prior[PMAX];    // exact rank of each input priority

// order-preserving u32 transform of float (total order matching IEEE <)
__device__ __forceinline__ u32 okey(float v) {
    u32 b = __float_as_uint(v);
    return (b & 0x80000000u) ? ~b : (b | 0x80000000u);
}
// monotone bucketing (exactness NOT required; monotone + equal-on-equal is)
__device__ __forceinline__ int bucketOf(float v) {
    if (!(v > 0.0f)) return 0;
    if (v >= 1.0f)   return NB - 1;
    int b = (int)(v * 65536.0f);
    return b < 0 ? 0 : (b > NB - 1 ? NB - 1 : b);
}

// ---------------------------------------------------------------------------
// Rank pipeline: hist -> scan -> scatter -> per-value rank
// rank(v) = #{candidate u : u < v}, candidates = scores[0..N) ∪ priorities[0..P)
// ---------------------------------------------------------------------------
__global__ void k_zero() {
    int i = blockIdx.x * blockDim.x + threadIdx.x;
    if (i < NB) g_hist[i] = 0u;
}

__global__ void k_hist(const float* __restrict__ scores,
                       const float* __restrict__ priorities, int N, int P) {
    int i = blockIdx.x * blockDim.x + threadIdx.x;
    if (i >= N + P) return;
    float v = (i < N) ? scores[i] : priorities[i - N];
    atomicAdd(&g_hist[bucketOf(v)], 1u);
}

__global__ __launch_bounds__(1024, 1) void k_scan() {
    __shared__ u32 wsum[32];
    const int tid = threadIdx.x;
    const int CPT = NB / 1024;            // 64 per thread
    const int base = tid * CPT;
    u32 s = 0;
    #pragma unroll 8
    for (int j = 0; j < CPT; ++j) s += g_hist[base + j];

    const int lane = tid & 31, wid = tid >> 5;
    u32 v = s;
    #pragma unroll
    for (int o = 1; o < 32; o <<= 1) {
        u32 t = __shfl_up_sync(0xFFFFFFFFu, v, o);
        if (lane >= o) v += t;
    }
    if (lane == 31) wsum[wid] = v;
    __syncthreads();
    if (wid == 0) {
        u32 w = wsum[lane];
        #pragma unroll
        for (int o = 1; o < 32; o <<= 1) {
            u32 t = __shfl_up_sync(0xFFFFFFFFu, w, o);
            if (lane >= o) w += t;
        }
        wsum[lane] = w;
    }
    __syncthreads();
    u32 run = (v - s) + ((wid > 0) ? wsum[wid - 1] : 0u);
    #pragma unroll 8
    for (int j = 0; j < CPT; ++j) {
        u32 h = g_hist[base + j];
        g_prefix[base + j] = run;
        g_cursor[base + j] = run;
        run += h;
    }
}

__global__ void k_scatter(const float* __restrict__ scores,
                          const float* __restrict__ priorities, int N, int P) {
    int i = blockIdx.x * blockDim.x + threadIdx.x;
    if (i >= N + P) return;
    float v = (i < N) ? scores[i] : priorities[i - N];
    u32 pos = atomicAdd(&g_cursor[bucketOf(v)], 1u);
    g_bdata[pos] = okey(v);
}

__global__ void k_rank(const float* __restrict__ scores,
                       const float* __restrict__ priorities, int N, int P) {
    int i = blockIdx.x * blockDim.x + threadIdx.x;
    if (i >= N + P) return;
    float v = (i < N) ? scores[i] : priorities[i - N];
    u16 r;
    if (!(v > 0.0f)) {
        r = 0;   // no negative candidates -> rank(<=0)=0 (skips the big zero bucket)
    } else {
        int b = bucketOf(v);
        u32 k = okey(v);
        u32 base = g_prefix[b];
        u32 n = g_hist[b];
        u32 c = 0;
        for (u32 j = 0; j < n; ++j) c += (g_bdata[base + j] < k) ? 1u : 0u;
        r = (u16)(base + c);   // < N+P = 20480 < 2^15
    }
    if (i < N) g_rank_scores[i] = r; else g_rank_prior[i - N] = r;
}

// ---------------------------------------------------------------------------
// k_sim: classify + exact sequential replace-phase in one block.
//
// Identity used: eviction sequence = ascending sorted order of evicted keys,
// and keys inserted during phase 2 always have rank > the rank just evicted.
// So pops come from TWO monotone sources:
//   (1) sorted initial-pool key list (parallel counting-sort; pointer walk)
//   (2) forward-only bitmap bucket queue over inserted keys
// key = (rank<<12)|slot -> u32 min == argmin with first-index tie-break.
// Stream element e = (rank<<14)|item; accept iff e >= th, th=(minRank+1)<<14.
// ---------------------------------------------------------------------------
__global__ __launch_bounds__(1024, 1)
void k_sim(const float* __restrict__ scores,
           const float* __restrict__ priorities,
           const int* __restrict__ countp,
           float* __restrict__ out,
           int N, int P, int D, long long out_size) {
    extern __shared__ u32 S[];
    u32*  pe    = S;                       // NMAX+8: staged scores, then tagged stream
    u32*  hist  = pe + (NMAX + 8);         // RMAX u32 (build) / ms16 u16 (serial)
    u32*  ps    = hist + RMAX;             // PMAX+4 sorted pool keys (+sentinels)
    u32*  bm    = ps + (PMAX + 4);         // BMW inserted-presence bitmap
    u32*  dbm   = bm + BMW;                // BMW dup-flag bitmap
    u32*  ovf   = dbm + BMW;               // OVF_CAP tie overflow (serial only)
    u16*  wr    = (u16*)(ovf + OVF_CAP);   // PMAX writer map
    u16*  items = (u16*)hist;              // alias: phase-2 items live BEFORE hist
    u16*  ms16  = (u16*)hist;              // alias: min-slot per rank (serial phase)
    __shared__ int wsum[32];
    __shared__ int sflag;

    const int tid = threadIdx.x;
    const int nthr = blockDim.x;
    const int lane = tid & 31, wid = tid >> 5;

    // ---- stage scores into pe (coalesced); init writer map ----
    for (int i = tid; i < NMAX; i += nthr)
        pe[i] = (i < N) ? __float_as_uint(scores[i]) : 0u;
    for (int i = tid; i < PMAX; i += nthr) wr[i] = 0xFFFFu;
    __syncthreads();

    // ---- classify: per-thread chunk of 16, counts from smem ----
    const int C0 = *countp;
    const int CH = NMAX / 1024;            // 16
    const int start = tid * CH;
    int c = 0;
    #pragma unroll
    for (int j = 0; j < CH; ++j)
        c += (__uint_as_float(pe[start + j]) > 0.5f) ? 1 : 0;

    int v = c;
    #pragma unroll
    for (int o = 1; o < 32; o <<= 1) {
        int t = __shfl_up_sync(0xFFFFFFFFu, v, o);
        if (lane >= o) v += t;
    }
    if (lane == 31) wsum[wid] = v;
    __syncthreads();
    if (wid == 0) {
        int w = wsum[lane];
        #pragma unroll
        for (int o = 1; o < 32; o <<= 1) {
            int t = __shfl_up_sync(0xFFFFFFFFu, w, o);
            if (lane >= o) w += t;
        }
        wsum[lane] = w;
    }
    __syncthreads();

    const int excl = (v - c) + ((wid > 0) ? wsum[wid - 1] : 0);
    const int total = wsum[(nthr >> 5) - 1];
    int room = P - C0; if (room < 0) room = 0;
    const int T  = (total > room) ? total - room : 0;
    const int fc = C0 + ((total < room) ? total : room);

    {   // second pass: appends -> wr, phase-2 items -> items[] (hist alias)
        int r = excl;
        #pragma unroll
        for (int j = 0; j < CH; ++j) {
            int i = start + j;
            if (__uint_as_float(pe[i]) > 0.5f) {
                if (r < room) wr[C0 + r] = (u16)i;
                else          items[r - room] = (u16)i;
                r++;
            }
        }
    }
    __syncthreads();

    // ---- tag stream: pe[q] = (rank<<14)|item ; pad -> 0 (always skipped) ----
    const int Tpad = (T + 7) & ~7;
    for (int q = tid; q < Tpad; q += nthr) {
        u32 e = 0u;
        if (q < T) {
            u32 it = (u32)items[q];
            e = ((u32)g_rank_scores[it] << 14) | it;
        }
        pe[q] = e;        // pe scores no longer needed
    }
    __syncthreads();      // items[] fully consumed before hist reuse

    if (T > 0) {
        // ---- counting-sort initial-pool keys by rank ----
        for (int i = tid; i < RMAX; i += nthr) hist[i] = 0u;
        __syncthreads();
        for (int i = tid; i < P; i += nthr) {
            u16 w = wr[i];
            u32 rk = (w != 0xFFFFu) ? (u32)g_rank_scores[w] : (u32)g_rank_prior[i];
            atomicAdd(&hist[rk], 1u);
        }
        __syncthreads();
        {   // exclusive prefix over RMAX (20/thread + block scan), hist -> cursor
            const int CPT = RMAX / 1024;   // 20
            const int base = tid * CPT;
            u32 s = 0;
            #pragma unroll
            for (int j = 0; j < CPT; ++j) s += hist[base + j];
            u32 vv = s;
            #pragma unroll
            for (int o = 1; o < 32; o <<= 1) {
                u32 t = __shfl_up_sync(0xFFFFFFFFu, vv, o);
                if (lane >= o) vv += t;
            }
            if (lane == 31) wsum[wid] = (int)vv;
            __syncthreads();
            if (wid == 0) {
                u32 w = (u32)wsum[lane];
                #pragma unroll
                for (int o = 1; o < 32; o <<= 1) {
                    u32 t = __shfl_up_sync(0xFFFFFFFFu, w, o);
                    if (lane >= o) w += t;
                }
                wsum[lane] = (int)w;
            }
            __syncthreads();
            u32 run = (vv - s) + ((wid > 0) ? (u32)wsum[wid - 1] : 0u);
            #pragma unroll
            for (int j = 0; j < CPT; ++j) {
                u32 h = hist[base + j];
                hist[base + j] = run;
                run += h;
            }
            __syncthreads();
        }
        for (int i = tid; i < P; i += nthr) {
            u16 w = wr[i];
            u32 rk = (w != 0xFFFFu) ? (u32)g_rank_scores[w] : (u32)g_rank_prior[i];
            u32 pos = atomicAdd(&hist[rk], 1u);
            ps[pos] = (rk << 12) | (u32)i;
        }
        for (int i = tid; i < 4; i += nthr) ps[P + i] = 0xFFFFFFFFu;  // sentinels
        __syncthreads();
        // odd-even cleanup for exact same-rank ties (groups tiny; loop to fixpoint)
        for (int it = 0; it < P; ++it) {
            if (tid == 0) sflag = 0;
            __syncthreads();
            for (int i = tid * 2; i + 1 < P; i += nthr * 2) {
                u32 a = ps[i], b = ps[i + 1];
                if (a > b) { ps[i] = b; ps[i + 1] = a; sflag = 1; }
            }
            __syncthreads();
            for (int i = tid * 2 + 1; i + 1 < P; i += nthr * 2) {
                u32 a = ps[i], b = ps[i + 1];
                if (a > b) { ps[i] = b; ps[i + 1] = a; sflag = 1; }
            }
            __syncthreads();
            if (sflag == 0) break;
        }
        // zero inserted-queue bitmaps (ms16 needs no init: read only after bit set)
        for (int i = tid; i < BMW; i += nthr) { bm[i] = 0u; dbm[i] = 0u; }
        __syncthreads();
    }

    // ---- serial simulation (thread 0) ----
    if (tid == 0 && T > 0) {
        int p = 0;
        u32 pk = ps[0], pkn = ps[1];
        u32 ik = 0xFFFFFFFFu;                 // inserted-queue min (full key)
        int ovfN = 0;
        u32 m = pk;                           // pool min (ik empty initially)
        u32 th = ((m >> 12) + 1u) << 14;

        const uint4* pe4 = (const uint4*)pe;
        for (int q0 = 0; q0 < Tpad; q0 += 8) {
            uint4 A = pe4[q0 >> 2];
            uint4 B = pe4[(q0 >> 2) + 1];
            u32 mx = max(max(max(A.x, A.y), max(A.z, A.w)),
                         max(max(B.x, B.y), max(B.z, B.w)));
            if (mx < th) continue;            // threshold only rises
            u32 ev[8] = {A.x, A.y, A.z, A.w, B.x, B.y, B.z, B.w};
            #pragma unroll
            for (int k = 0; k < 8; ++k) {
                u32 e = ev[k];
                if (e < th) continue;

                // ---- pop overall min: merge of the two monotone sources ----
                u32 E;
                if (pk < ik) {
                    E = pk;
                    ++p;
                    pk = pkn;
                    pkn = ps[p + 1];          // prefetch next
                } else {
                    E = ik;
                    u32 rr = ik >> 12;
                    int w = rr >> 5;
                    u32 bit = 1u << (rr & 31);
                    if (dbm[w] & bit) {       // rare: duplicate-rank promote
                        u32 best = 0xFFFFFFFFu; int bi = -1; bool more = false;
                        for (int j = 0; j < ovfN; ++j) {
                            u32 o = ovf[j];
                            if ((o >> 12) == rr) {
                                if (o < best) {
                                    if (bi >= 0) more = true;
                                    best = o; bi = j;
                                } else more = true;
                            }
                        }
                        ovf[bi] = ovf[--ovfN];
                        if (!more) dbm[w] &= ~bit;
                        ms16[rr] = (u16)(best & 0xFFFu);
                        ik = best;
                    } else {
                        u32 bw = bm[w] & ~bit;
                        bm[w] = bw;
                        u32 mm = bw & (0xFFFFFFFEu << (rr & 31));
                        while (mm == 0u && ++w < BMW) mm = bm[w];
                        if (w >= BMW) ik = 0xFFFFFFFFu;
                        else {
                            u32 r2 = (u32)((w << 5) + (__ffs(mm) - 1));
                            ik = (r2 << 12) | (u32)ms16[r2];
                        }
                    }
                }

                // ---- write + push replacement key ----
                u32 slot = E & 0xFFFu;
                wr[slot] = (u16)(e & 0x3FFFu);
                u32 nr = e >> 14;
                u32 nk = (nr << 12) | slot;
                int wq = nr >> 5;
                u32 nbit = 1u << (nr & 31);
                u32 bw2 = bm[wq];
                if (bw2 & nbit) {             // rare: rank occupied
                    u32 ex = (nr << 12) | (u32)ms16[nr];
                    if (nk < ex) { ms16[nr] = (u16)slot; if (ovfN < OVF_CAP) ovf[ovfN++] = ex; }
                    else         { if (ovfN < OVF_CAP) ovf[ovfN++] = nk; }
                    dbm[wq] |= nbit;
                } else {
                    bm[wq] = bw2 | nbit;
                    ms16[nr] = (u16)slot;
                }
                ik = min(ik, nk);
                m = min(pk, ik);
                th = ((m >> 12) + 1u) << 14;
            }
        }
    }
    __syncthreads();

    // ---- epilogue: writer map out; priorities + count to output tail ----
    const long long base = (long long)P * (long long)D;
    for (int i = tid; i < P; i += nthr) {
        u16 w = wr[i];
        g_writer[i] = w;
        if (base + i < out_size)
            out[base + i] = (w != 0xFFFFu) ? scores[w] : priorities[i];
    }
    if (tid == 0 && base + P < out_size)
        out[base + P] = (float)fc;
}

// ---------------------------------------------------------------------------
// Row gather: one block per pool slot.
// ---------------------------------------------------------------------------
__global__ void k_copy(const float* __restrict__ pool,
                       const float* __restrict__ summaries,
                       float* __restrict__ out, int D) {
    const int row = blockIdx.x;
    const u16 w = g_writer[row];
    const float* src = (w == 0xFFFFu) ? (pool + (long long)row * D)
                                      : (summaries + (long long)w * D);
    float* dst = out + (long long)row * D;
    if ((D & 3) == 0) {
        const float4* s4 = (const float4*)src;
        float4* d4 = (float4*)dst;
        for (int i = threadIdx.x; i < (D >> 2); i += blockDim.x) d4[i] = s4[i];
    } else {
        for (int i = threadIdx.x; i < D; i += blockDim.x) dst[i] = src[i];
    }
}

// ---------------------------------------------------------------------------
// Inputs (metadata order): summaries[N,D] f32, scores[N] f32, pool[P,D] f32,
// priorities[P] f32, count i32 scalar.
// Output: concat(pool_out[P*D], priorities[P], count) as f32.
// ---------------------------------------------------------------------------
extern "C" void kernel_launch(void* const* d_in, const int* in_sizes, int n_in,
                              void* d_out, int out_size) {
    const float* summaries  = (const float*)d_in[0];
    const float* scores     = (const float*)d_in[1];
    const float* pool       = (const float*)d_in[2];
    const float* priorities = (const float*)d_in[3];
    const int*   countp     = (const int*)d_in[4];

    const int N = in_sizes[1];
    const int P = in_sizes[3];
    const int D = (N > 0) ? (in_sizes[0] / N) : 0;
    const int M = N + P;
    float* out = (float*)d_out;

    // smem (u32 words): pe + hist + ps + bm + dbm + ovf, plus wr (u16 PMAX)
    const int sim_smem = ((NMAX + 8) + RMAX + (PMAX + 4) + BMW + BMW + OVF_CAP) * 4
                       + PMAX * 2;   // 179,264 bytes
    cudaFuncSetAttribute(k_sim, cudaFuncAttributeMaxDynamicSharedMemorySize, sim_smem);

    k_zero   <<<NB / 256, 256>>>();
    k_hist   <<<(M + 255) / 256, 256>>>(scores, priorities, N, P);
    k_scan   <<<1, 1024>>>();
    k_scatter<<<(M + 255) / 256, 256>>>(scores, priorities, N, P);
    k_rank   <<<(M + 255) / 256, 256>>>(scores, priorities, N, P);
    k_sim    <<<1, 1024, sim_smem>>>(scores, priorities, countp, out,
                                     N, P, D, (long long)out_size);
    k_copy   <<<P, 256>>>(pool, summaries, out, D);
}

// round 8
// speedup vs baseline: 2.7132x; 2.6200x over previous
#include <cuda_runtime.h>
#include <cstdint>

// Problem constants (upper bounds; runtime shapes read from in_sizes)
#define NMAX 16384
#define PMAX 4096
#define NB   65536              // rank buckets for the ranking pipeline
#define RMAX (NMAX + PMAX)      // 20480 distinct ranks max

typedef unsigned int u32;
typedef unsigned short u16;

// -------- cross-kernel scratch (allocation-free: __device__ globals) --------
__device__ u16 g_writer[PMAX];        // last writer item per slot, 0xFFFF = keep original

__device__ u32 g_hist[NB];            // rank pipeline hist; later U-sort hist
__device__ u32 g_prefix[NB];          // rank pipeline prefix; later sortedU (gU)
__device__ u32 g_cursor[NB];          // rank pipeline cursors; later U cursors [0,RMAX) + par [RMAX,RMAX+16384)
__device__ u32 g_bdata[RMAX];         // rank pipeline bucket data; later accList
__device__ u16 g_rank_scores[NMAX];   // exact rank of each score
__device__ u16 g_rank_prior[PMAX];    // exact rank of each input priority

// order-preserving u32 transform of float (total order matching IEEE <)
__device__ __forceinline__ u32 okey(float v) {
    u32 b = __float_as_uint(v);
    return (b & 0x80000000u) ? ~b : (b | 0x80000000u);
}
// monotone bucketing (exactness NOT required; monotone + equal-on-equal is)
__device__ __forceinline__ int bucketOf(float v) {
    if (!(v > 0.0f)) return 0;
    if (v >= 1.0f)   return NB - 1;
    int b = (int)(v * 65536.0f);
    return b < 0 ? 0 : (b > NB - 1 ? NB - 1 : b);
}

// ---------------------------------------------------------------------------
// Rank pipeline (unchanged, known-good): hist -> scan -> scatter -> rank
// rank(v) = #{candidate u : u < v}, candidates = scores ∪ priorities
// ---------------------------------------------------------------------------
__global__ void k_zero() {
    int i = blockIdx.x * blockDim.x + threadIdx.x;
    if (i < NB) g_hist[i] = 0u;
}

__global__ void k_hist(const float* __restrict__ scores,
                       const float* __restrict__ priorities, int N, int P) {
    int i = blockIdx.x * blockDim.x + threadIdx.x;
    if (i >= N + P) return;
    float v = (i < N) ? scores[i] : priorities[i - N];
    atomicAdd(&g_hist[bucketOf(v)], 1u);
}

__global__ __launch_bounds__(1024, 1) void k_scan() {
    __shared__ u32 wsum[32];
    const int tid = threadIdx.x;
    const int CPT = NB / 1024;
    const int base = tid * CPT;
    u32 s = 0;
    #pragma unroll 8
    for (int j = 0; j < CPT; ++j) s += g_hist[base + j];

    const int lane = tid & 31, wid = tid >> 5;
    u32 v = s;
    #pragma unroll
    for (int o = 1; o < 32; o <<= 1) {
        u32 t = __shfl_up_sync(0xFFFFFFFFu, v, o);
        if (lane >= o) v += t;
    }
    if (lane == 31) wsum[wid] = v;
    __syncthreads();
    if (wid == 0) {
        u32 w = wsum[lane];
        #pragma unroll
        for (int o = 1; o < 32; o <<= 1) {
            u32 t = __shfl_up_sync(0xFFFFFFFFu, w, o);
            if (lane >= o) w += t;
        }
        wsum[lane] = w;
    }
    __syncthreads();
    u32 run = (v - s) + ((wid > 0) ? wsum[wid - 1] : 0u);
    #pragma unroll 8
    for (int j = 0; j < CPT; ++j) {
        u32 h = g_hist[base + j];
        g_prefix[base + j] = run;
        g_cursor[base + j] = run;
        run += h;
    }
}

__global__ void k_scatter(const float* __restrict__ scores,
                          const float* __restrict__ priorities, int N, int P) {
    int i = blockIdx.x * blockDim.x + threadIdx.x;
    if (i >= N + P) return;
    float v = (i < N) ? scores[i] : priorities[i - N];
    u32 pos = atomicAdd(&g_cursor[bucketOf(v)], 1u);
    g_bdata[pos] = okey(v);
}

__global__ void k_rank(const float* __restrict__ scores,
                       const float* __restrict__ priorities, int N, int P) {
    int i = blockIdx.x * blockDim.x + threadIdx.x;
    if (i >= N + P) return;
    float v = (i < N) ? scores[i] : priorities[i - N];
    u16 r;
    if (!(v > 0.0f)) {
        r = 0;
    } else {
        int b = bucketOf(v);
        u32 k = okey(v);
        u32 base = g_prefix[b];
        u32 n = g_hist[b];
        u32 c = 0;
        for (u32 j = 0; j < n; ++j) c += (g_bdata[base + j] < k) ? 1u : 0u;
        r = (u16)(base + c);
    }
    if (i < N) g_rank_scores[i] = r; else g_rank_prior[i - N] = r;
}

// binary lower bound over sorted u16: returns #elements < key
__device__ __forceinline__ int lb16(const u16* __restrict__ a, int n, u16 key) {
    int lo = 0, hi = n;
    while (lo < hi) { int m = (lo + hi) >> 1; if (a[m] < key) lo = m + 1; else hi = m; }
    return lo;
}

// ---------------------------------------------------------------------------
// k_final: fully parallel replacement of the serial simulation.
//  1. classify -> appends + phase-2 stream (si, T)
//  2. accept(q) <=> psBelow(r_q) + #{j<q: r_j<r_q} >= q+1   (parallel counts)
//  3. sort U = poolstart ∪ accepted by rank; accept j evicts sortedU[j]
//  4. slot chains via pointer jumping; intra-rank tie groups fixpoint by slot
//  5. survivors (positions >= A) define final writer map
// ---------------------------------------------------------------------------
__global__ __launch_bounds__(1024, 1)
void k_final(const float* __restrict__ scores,
             const float* __restrict__ priorities,
             const int* __restrict__ countp,
             float* __restrict__ out,
             int N, int P, int D, long long out_size) {
    extern __shared__ u32 S[];
    u32* buf   = S;                          // 16384 w: staged score bits; later chunkS in first 8192
    u16* sr    = (u16*)(S + 16384);          // 16384 stream ranks
    u16* si    = (u16*)(S + 16384 + 8192);   // 16384 stream item ids
    u16* psr   = (u16*)(S + 16384 + 16384);  // 4096 poolstart ranks
    u16* psrS  = (u16*)(S + 16384 + 16384 + 2048); // 4096 sorted poolstart ranks
    u16* wr    = (u16*)(S + 16384 + 16384 + 4096); // 4096 writer map
    u32* Bq    = S + 16384 + 16384 + 6144;   // 16384 cross-chunk below-counts
    u16* chunkS = (u16*)buf;                 // alias (scores dead after classify)
    __shared__ int wsum[32];
    __shared__ int sh_changed, sh_anyTies;

    u32* gU  = g_prefix;                 // sorted U (P+A <= 20480)
    u32* par = g_cursor + RMAX;          // chain parents (A <= 16384)

    const int tid = threadIdx.x;
    const int nthr = blockDim.x;
    const int lane = tid & 31, wid = tid >> 5;

    // ---- phase 0: stage scores, init writer map ----
    for (int i = tid; i < NMAX; i += nthr)
        buf[i] = (i < N) ? __float_as_uint(scores[i]) : 0u;
    for (int i = tid; i < PMAX; i += nthr) wr[i] = 0xFFFFu;
    __syncthreads();

    // ---- phase 1: classify (chunked 16/thread over smem-staged scores) ----
    const int C0 = *countp;
    const int CH = NMAX / 1024;
    const int start = tid * CH;
    int c = 0;
    #pragma unroll
    for (int j = 0; j < CH; ++j)
        c += (__uint_as_float(buf[start + j]) > 0.5f) ? 1 : 0;

    int v = c;
    #pragma unroll
    for (int o = 1; o < 32; o <<= 1) {
        int t = __shfl_up_sync(0xFFFFFFFFu, v, o);
        if (lane >= o) v += t;
    }
    if (lane == 31) wsum[wid] = v;
    __syncthreads();
    if (wid == 0) {
        int w = wsum[lane];
        #pragma unroll
        for (int o = 1; o < 32; o <<= 1) {
            int t = __shfl_up_sync(0xFFFFFFFFu, w, o);
            if (lane >= o) w += t;
        }
        wsum[lane] = w;
    }
    __syncthreads();
    const int excl = (v - c) + ((wid > 0) ? wsum[wid - 1] : 0);
    const int total = wsum[(nthr >> 5) - 1];
    int room = P - C0; if (room < 0) room = 0;
    const int T  = (total > room) ? total - room : 0;
    const int fc = C0 + ((total < room) ? total : room);
    {
        int r = excl;
        #pragma unroll
        for (int j = 0; j < CH; ++j) {
            int i = start + j;
            if (__uint_as_float(buf[i]) > 0.5f) {
                if (r < room) wr[C0 + r] = (u16)i;
                else          si[r - room] = (u16)i;
                r++;
            }
        }
    }
    __syncthreads();

    // ---- phase 2: stream ranks + poolstart ranks ----
    for (int q = tid; q < T; q += nthr) sr[q] = g_rank_scores[si[q]];
    for (int i = tid; i < PMAX; i += nthr) {
        u16 pr = 0xFFFFu;
        if (i < P) {
            u16 w = wr[i];
            pr = (w != 0xFFFFu) ? g_rank_scores[w] : g_rank_prior[i];
        }
        psr[i] = pr;
        psrS[i] = pr;
    }
    __syncthreads();

    int A = 0;

    if (T > 0) {
        // ---- phase 3a: block bitonic sort of psrS (4096 u16 ascending) ----
        for (int k = 2; k <= 4096; k <<= 1) {
            for (int j = k >> 1; j > 0; j >>= 1) {
                for (int idx = tid; idx < 4096; idx += nthr) {
                    int p = idx ^ j;
                    if (p > idx) {
                        u16 x = psrS[idx], y = psrS[p];
                        bool up = ((idx & k) == 0);
                        if (up ? (x > y) : (x < y)) { psrS[idx] = y; psrS[p] = x; }
                    }
                }
                __syncthreads();
            }
        }

        // ---- phase 3b: per-warp bitonic sorts of 256-chunks of stream ranks ----
        const int NCH = (T + 255) >> 8;
        for (int i = tid; i < (NCH << 8); i += nthr)
            chunkS[i] = (i < T) ? sr[i] : (u16)0xFFFFu;
        __syncthreads();
        for (int ch = wid; ch < NCH; ch += 32) {
            u16* a = chunkS + (ch << 8);
            for (int k = 2; k <= 256; k <<= 1) {
                for (int j = k >> 1; j > 0; j >>= 1) {
                    for (int idx = lane; idx < 256; idx += 32) {
                        int p = idx ^ j;
                        if (p > idx) {
                            u16 x = a[idx], y = a[p];
                            bool up = ((idx & k) == 0);
                            if (up ? (x > y) : (x < y)) { a[idx] = y; a[p] = x; }
                        }
                    }
                    __syncwarp();
                }
            }
        }
        __syncthreads();

        // ---- phase 3c: cross-chunk below-counts, pair-parallel ----
        for (int q = tid; q < T; q += nthr) Bq[q] = 0u;
        __syncthreads();
        {
            const int pairs = T * NCH;
            for (int idx = tid; idx < pairs; idx += nthr) {
                int q = idx / NCH;
                int c2 = idx - q * NCH;
                if (c2 < (q >> 8)) {
                    int cnt = lb16(chunkS + (c2 << 8), 256, sr[q]);
                    if (cnt) atomicAdd(&Bq[q], (u32)cnt);
                }
            }
        }
        __syncthreads();

        // ---- phase 4: accept decisions + compaction ----
        int myCnt = 0;
        u32 amask = 0;
        const int q0 = tid * 16;
        #pragma unroll
        for (int j = 0; j < 16; ++j) {
            int q = q0 + j;
            if (q < T) {
                u16 r = sr[q];
                int b = (int)Bq[q];
                int base = q & ~255;
                for (int jj = base; jj < q; ++jj) b += (sr[jj] < r) ? 1 : 0;
                int psb = lb16(psrS, 4096, r);
                if (psb + b >= q + 1) { amask |= (1u << j); myCnt++; }
            }
        }
        // block scan of myCnt
        int vv = myCnt;
        #pragma unroll
        for (int o = 1; o < 32; o <<= 1) {
            int t = __shfl_up_sync(0xFFFFFFFFu, vv, o);
            if (lane >= o) vv += t;
        }
        if (lane == 31) wsum[wid] = vv;
        __syncthreads();
        if (wid == 0) {
            int w = wsum[lane];
            #pragma unroll
            for (int o = 1; o < 32; o <<= 1) {
                int t = __shfl_up_sync(0xFFFFFFFFu, w, o);
                if (lane >= o) w += t;
            }
            wsum[lane] = w;
        }
        __syncthreads();
        int jbase = (vv - myCnt) + ((wid > 0) ? wsum[wid - 1] : 0);
        A = wsum[(nthr >> 5) - 1];
        #pragma unroll
        for (int j = 0; j < 16; ++j) {
            if (amask & (1u << j)) {
                int q = q0 + j;
                g_bdata[jbase++] = ((u32)sr[q] << 14) | (u32)si[q];
            }
        }
        __syncthreads();
    }

    if (A > 0) {
        const int UN = P + A;

        // ---- phase 5: counting sort of U by rank into gU ----
        for (int i = tid; i < RMAX; i += nthr) g_hist[i] = 0u;
        __syncthreads();
        for (int i = tid; i < P; i += nthr) atomicAdd(&g_hist[psr[i]], 1u);
        for (int j = tid; j < A; j += nthr) atomicAdd(&g_hist[g_bdata[j] >> 14], 1u);
        __syncthreads();
        {   // exclusive prefix over RMAX -> g_cursor
            const int CPT = RMAX / 1024;   // 20
            const int base = tid * CPT;
            u32 s = 0;
            #pragma unroll
            for (int j = 0; j < CPT; ++j) s += g_hist[base + j];
            u32 vv = s;
            #pragma unroll
            for (int o = 1; o < 32; o <<= 1) {
                u32 t = __shfl_up_sync(0xFFFFFFFFu, vv, o);
                if (lane >= o) vv += t;
            }
            if (lane == 31) wsum[wid] = (int)vv;
            __syncthreads();
            if (wid == 0) {
                u32 w = (u32)wsum[lane];
                #pragma unroll
                for (int o = 1; o < 32; o <<= 1) {
                    u32 t = __shfl_up_sync(0xFFFFFFFFu, w, o);
                    if (lane >= o) w += t;
                }
                wsum[lane] = (int)w;
            }
            __syncthreads();
            u32 run = (vv - s) + ((wid > 0) ? (u32)wsum[wid - 1] : 0u);
            #pragma unroll
            for (int j = 0; j < CPT; ++j) {
                u32 h = g_hist[base + j];
                g_cursor[base + j] = run;
                run += h;
            }
            __syncthreads();
        }
        // scatter: elem = rank<<17 | type<<16 | id
        for (int i = tid; i < P; i += nthr) {
            u32 r = psr[i];
            u32 pos = atomicAdd(&g_cursor[r], 1u);
            gU[pos] = (r << 17) | (u32)i;
        }
        for (int j = tid; j < A; j += nthr) {
            u32 r = g_bdata[j] >> 14;
            u32 pos = atomicAdd(&g_cursor[r], 1u);
            gU[pos] = (r << 17) | 0x10000u | (u32)j;
        }
        __syncthreads();

        // ---- phase 6: tie detection + fixpoint chain resolution ----
        if (tid == 0) sh_anyTies = 0;
        __syncthreads();
        for (int p = tid; p + 1 < UN; p += nthr)
            if ((gU[p] >> 17) == (gU[p + 1] >> 17)) sh_anyTies = 1;
        __syncthreads();

        const int MAXIT = 32;
        for (int it = 0; it < MAXIT; ++it) {
            // build parents: accept j evicts gU[j]
            for (int j = tid; j < A; j += nthr) {
                u32 e = gU[j];
                par[j] = (e & 0x10000u) ? (e & 0xFFFFu) : (0x80000000u | (e & 0xFFFFu));
            }
            __syncthreads();
            for (int rd = 0; rd < 15; ++rd) {
                for (int j = tid; j < A; j += nthr) {
                    u32 pv = par[j];
                    if (!(pv & 0x80000000u)) par[j] = par[pv];
                }
                __syncthreads();
            }
            if (!sh_anyTies) break;
            if (it == MAXIT - 1) break;
            if (tid == 0) sh_changed = 0;
            __syncthreads();
            // reorder tie groups by slot (leader thread per group; ranks stable)
            for (int p = tid; p < UN; p += nthr) {
                u32 r = gU[p] >> 17;
                bool leader = (p == 0) || ((gU[p - 1] >> 17) != r);
                if (leader && p + 1 < UN && (gU[p + 1] >> 17) == r) {
                    int len = 1;
                    while (p + len < UN && (gU[p + len] >> 17) == r) len++;
                    bool ch = false;
                    for (int a = 1; a < len; ++a) {
                        u32 x = gU[p + a];
                        u32 sx = (x & 0x10000u) ? (par[x & 0xFFFFu] & 0xFFFFu) : (x & 0xFFFFu);
                        u32 kx = (sx << 1) | ((x >> 16) & 1u);
                        int b = a;
                        while (b > 0) {
                            u32 y = gU[p + b - 1];
                            u32 sy = (y & 0x10000u) ? (par[y & 0xFFFFu] & 0xFFFFu) : (y & 0xFFFFu);
                            u32 ky = (sy << 1) | ((y >> 16) & 1u);
                            if (ky <= kx) break;
                            gU[p + b] = y; b--; ch = true;
                        }
                        gU[p + b] = x;
                    }
                    if (ch) sh_changed = 1;
                }
            }
            __syncthreads();
            if (!sh_changed) break;
        }

        // ---- phase 7: survivors (positions >= A) write the final map ----
        for (int pos = A + tid; pos < UN; pos += nthr) {
            u32 e = gU[pos];
            if (e & 0x10000u) {
                u32 j = e & 0xFFFFu;
                u32 s = par[j] & 0xFFFFu;
                if (s < (u32)P) wr[s] = (u16)(g_bdata[j] & 0x3FFFu);
            }
        }
        __syncthreads();
    }

    // ---- epilogue: writer map out; priorities + count to output tail ----
    const long long obase = (long long)P * (long long)D;
    for (int i = tid; i < P; i += nthr) {
        u16 w = wr[i];
        g_writer[i] = w;
        if (obase + i < out_size)
            out[obase + i] = (w != 0xFFFFu) ? scores[w] : priorities[i];
    }
    if (tid == 0 && obase + P < out_size)
        out[obase + P] = (float)fc;
}

// ---------------------------------------------------------------------------
// Row gather: one block per pool slot.
// ---------------------------------------------------------------------------
__global__ void k_copy(const float* __restrict__ pool,
                       const float* __restrict__ summaries,
                       float* __restrict__ out, int D) {
    const int row = blockIdx.x;
    const u16 w = g_writer[row];
    const float* src = (w == 0xFFFFu) ? (pool + (long long)row * D)
                                      : (summaries + (long long)w * D);
    float* dst = out + (long long)row * D;
    if ((D & 3) == 0) {
        const float4* s4 = (const float4*)src;
        float4* d4 = (float4*)dst;
        for (int i = threadIdx.x; i < (D >> 2); i += blockDim.x) d4[i] = s4[i];
    } else {
        for (int i = threadIdx.x; i < D; i += blockDim.x) dst[i] = src[i];
    }
}

// ---------------------------------------------------------------------------
// Inputs (metadata order): summaries[N,D] f32, scores[N] f32, pool[P,D] f32,
// priorities[P] f32, count i32 scalar.
// Output: concat(pool_out[P*D], priorities[P], count) as f32.
// ---------------------------------------------------------------------------
extern "C" void kernel_launch(void* const* d_in, const int* in_sizes, int n_in,
                              void* d_out, int out_size) {
    const float* summaries  = (const float*)d_in[0];
    const float* scores     = (const float*)d_in[1];
    const float* pool       = (const float*)d_in[2];
    const float* priorities = (const float*)d_in[3];
    const int*   countp     = (const int*)d_in[4];

    const int N = in_sizes[1];
    const int P = in_sizes[3];
    const int D = (N > 0) ? (in_sizes[0] / N) : 0;
    const int M = N + P;
    float* out = (float*)d_out;

    // smem words: buf 16384 + sr 8192 + si 8192 + psr 2048 + psrS 2048
    //           + wr 2048 + Bq 16384 = 55296 words = 221184 bytes
    const int fin_smem = 55296 * 4;
    cudaFuncSetAttribute(k_final, cudaFuncAttributeMaxDynamicSharedMemorySize, fin_smem);

    k_zero   <<<NB / 256, 256>>>();
    k_hist   <<<(M + 255) / 256, 256>>>(scores, priorities, N, P);
    k_scan   <<<1, 1024>>>();
    k_scatter<<<(M + 255) / 256, 256>>>(scores, priorities, N, P);
    k_rank   <<<(M + 255) / 256, 256>>>(scores, priorities, N, P);
    k_final  <<<1, 1024, fin_smem>>>(scores, priorities, countp, out,
                                     N, P, D, (long long)out_size);
    k_copy   <<<P, 256>>>(pool, summaries, out, D);
}

// round 9
// speedup vs baseline: 2.9174x; 1.0752x over previous
#include <cuda_runtime.h>
#include <cstdint>

// Problem constants (upper bounds; runtime shapes read from in_sizes)
#define NMAX 16384
#define PMAX 4096
#define NB   65536              // rank buckets for the ranking pipeline
#define RMAX (NMAX + PMAX)      // 20480 distinct ranks max

typedef unsigned int u32;
typedef unsigned short u16;

// -------- cross-kernel scratch (allocation-free: __device__ globals) --------
__device__ u16 g_writer[PMAX];        // last writer item per slot, 0xFFFF = keep original

__device__ u32 g_hist[NB];            // rank pipeline hist; later pool/U rank hist
__device__ u32 g_prefix[NB];          // rank pipeline prefix
__device__ u32 g_cursor[NB];          // rank pipeline cursors; later psBelow / U cursors
__device__ u32 g_bdata[RMAX];         // rank pipeline bucket data; later accList
__device__ u16 g_rank_scores[NMAX];   // exact rank of each score
__device__ u16 g_rank_prior[PMAX];    // exact rank of each input priority

// order-preserving u32 transform of float (total order matching IEEE <)
__device__ __forceinline__ u32 okey(float v) {
    u32 b = __float_as_uint(v);
    return (b & 0x80000000u) ? ~b : (b | 0x80000000u);
}
// monotone bucketing (exactness NOT required; monotone + equal-on-equal is)
__device__ __forceinline__ int bucketOf(float v) {
    if (!(v > 0.0f)) return 0;
    if (v >= 1.0f)   return NB - 1;
    int b = (int)(v * 65536.0f);
    return b < 0 ? 0 : (b > NB - 1 ? NB - 1 : b);
}

// ---------------------------------------------------------------------------
// Rank pipeline (unchanged, known-good): hist -> scan -> scatter -> rank
// ---------------------------------------------------------------------------
__global__ void k_zero() {
    int i = blockIdx.x * blockDim.x + threadIdx.x;
    if (i < NB) g_hist[i] = 0u;
}

__global__ void k_hist(const float* __restrict__ scores,
                       const float* __restrict__ priorities, int N, int P) {
    int i = blockIdx.x * blockDim.x + threadIdx.x;
    if (i >= N + P) return;
    float v = (i < N) ? scores[i] : priorities[i - N];
    atomicAdd(&g_hist[bucketOf(v)], 1u);
}

__global__ __launch_bounds__(1024, 1) void k_scan() {
    __shared__ u32 wsum[32];
    const int tid = threadIdx.x;
    const int CPT = NB / 1024;
    const int base = tid * CPT;
    u32 s = 0;
    #pragma unroll 8
    for (int j = 0; j < CPT; ++j) s += g_hist[base + j];

    const int lane = tid & 31, wid = tid >> 5;
    u32 v = s;
    #pragma unroll
    for (int o = 1; o < 32; o <<= 1) {
        u32 t = __shfl_up_sync(0xFFFFFFFFu, v, o);
        if (lane >= o) v += t;
    }
    if (lane == 31) wsum[wid] = v;
    __syncthreads();
    if (wid == 0) {
        u32 w = wsum[lane];
        #pragma unroll
        for (int o = 1; o < 32; o <<= 1) {
            u32 t = __shfl_up_sync(0xFFFFFFFFu, w, o);
            if (lane >= o) w += t;
        }
        wsum[lane] = w;
    }
    __syncthreads();
    u32 run = (v - s) + ((wid > 0) ? wsum[wid - 1] : 0u);
    #pragma unroll 8
    for (int j = 0; j < CPT; ++j) {
        u32 h = g_hist[base + j];
        g_prefix[base + j] = run;
        g_cursor[base + j] = run;
        run += h;
    }
}

__global__ void k_scatter(const float* __restrict__ scores,
                          const float* __restrict__ priorities, int N, int P) {
    int i = blockIdx.x * blockDim.x + threadIdx.x;
    if (i >= N + P) return;
    float v = (i < N) ? scores[i] : priorities[i - N];
    u32 pos = atomicAdd(&g_cursor[bucketOf(v)], 1u);
    g_bdata[pos] = okey(v);
}

__global__ void k_rank(const float* __restrict__ scores,
                       const float* __restrict__ priorities, int N, int P) {
    int i = blockIdx.x * blockDim.x + threadIdx.x;
    if (i >= N + P) return;
    float v = (i < N) ? scores[i] : priorities[i - N];
    u16 r;
    if (!(v > 0.0f)) {
        r = 0;
    } else {
        int b = bucketOf(v);
        u32 k = okey(v);
        u32 base = g_prefix[b];
        u32 n = g_hist[b];
        u32 c = 0;
        for (u32 j = 0; j < n; ++j) c += (g_bdata[base + j] < k) ? 1u : 0u;
        r = (u16)(base + c);
    }
    if (i < N) g_rank_scores[i] = r; else g_rank_prior[i - N] = r;
}

// binary lower bound over sorted u16: returns #elements < key
__device__ __forceinline__ int lb16(const u16* __restrict__ a, int n, u16 key) {
    int lo = 0, hi = n;
    while (lo < hi) { int m = (lo + hi) >> 1; if (a[m] < key) lo = m + 1; else hi = m; }
    return lo;
}

// ---- smem word offsets (u32 words) for k_final ----
#define OFF_BUF   0                         // 16384 w
#define OFF_SR    16384                     // 8192 w  (16384 u16)
#define OFF_SI    24576                     // 8192 w
#define OFF_BQ    32768                     // 16384 w
#define OFF_PSR   49152                     // 2048 w  (4096 u16)
#define OFF_WR    51200                     // 2048 w
#define SMEM_WORDS 53248                    // 212,992 bytes
// Phase-B aliases over dead regions (buf/sr/si/Bq dead after phase 4):
#define OFF_GU    0                         // 20480 w  (buf + sr head)
#define OFF_PAR   20480                     // 16384 w  (sr tail + si + Bq head)

// ---------------------------------------------------------------------------
// k_final: fully parallel simulation.
//  1. classify -> appends + phase-2 stream (si, T)
//  2. accept(q) <=> psBelow[r_q] + #{j<q: r_j<r_q} >= q+1
//     psBelow = exclusive prefix of pool-rank histogram (NO bitonic sort)
//  3. sort U = poolstart ∪ accepted by rank (counting); accept j evicts gU[j]
//  4. slot chains via early-exit pointer jumping (smem); tie fixpoint by slot
//  5. survivors (positions >= A) define final writer map
// ---------------------------------------------------------------------------
__global__ __launch_bounds__(1024, 1)
void k_final(const float* __restrict__ scores,
             const float* __restrict__ priorities,
             const int* __restrict__ countp,
             float* __restrict__ out,
             int N, int P, int D, long long out_size) {
    extern __shared__ u32 S[];
    u32* buf    = S + OFF_BUF;
    u16* sr     = (u16*)(S + OFF_SR);
    u16* si     = (u16*)(S + OFF_SI);
    u32* Bq     = S + OFF_BQ;
    u16* psr    = (u16*)(S + OFF_PSR);
    u16* wr     = (u16*)(S + OFF_WR);
    u16* chunkS = (u16*)buf;                 // alias, phases 3b-3c only
    u32* gU     = S + OFF_GU;                // alias, phases 5-7
    u32* par    = S + OFF_PAR;               // alias, phases 6-7
    __shared__ int wsum[32];
    __shared__ int sh_changed, sh_anyTies;

    const int tid = threadIdx.x;
    const int nthr = blockDim.x;
    const int lane = tid & 31, wid = tid >> 5;

    // ---- phase 0: stage scores, init writer map ----
    for (int i = tid; i < NMAX; i += nthr)
        buf[i] = (i < N) ? __float_as_uint(scores[i]) : 0u;
    for (int i = tid; i < PMAX; i += nthr) wr[i] = 0xFFFFu;
    __syncthreads();

    // ---- phase 1: classify ----
    const int C0 = *countp;
    const int CH = NMAX / 1024;
    const int start = tid * CH;
    int c = 0;
    #pragma unroll
    for (int j = 0; j < CH; ++j)
        c += (__uint_as_float(buf[start + j]) > 0.5f) ? 1 : 0;

    int v = c;
    #pragma unroll
    for (int o = 1; o < 32; o <<= 1) {
        int t = __shfl_up_sync(0xFFFFFFFFu, v, o);
        if (lane >= o) v += t;
    }
    if (lane == 31) wsum[wid] = v;
    __syncthreads();
    if (wid == 0) {
        int w = wsum[lane];
        #pragma unroll
        for (int o = 1; o < 32; o <<= 1) {
            int t = __shfl_up_sync(0xFFFFFFFFu, w, o);
            if (lane >= o) w += t;
        }
        wsum[lane] = w;
    }
    __syncthreads();
    const int excl = (v - c) + ((wid > 0) ? wsum[wid - 1] : 0);
    const int total = wsum[(nthr >> 5) - 1];
    int room = P - C0; if (room < 0) room = 0;
    const int T  = (total > room) ? total - room : 0;
    const int fc = C0 + ((total < room) ? total : room);
    {
        int r = excl;
        #pragma unroll
        for (int j = 0; j < CH; ++j) {
            int i = start + j;
            if (__uint_as_float(buf[i]) > 0.5f) {
                if (r < room) wr[C0 + r] = (u16)i;
                else          si[r - room] = (u16)i;
                r++;
            }
        }
    }
    __syncthreads();

    // ---- phase 2: stream ranks + poolstart ranks ----
    for (int q = tid; q < T; q += nthr) sr[q] = g_rank_scores[si[q]];
    for (int i = tid; i < PMAX; i += nthr) {
        u16 pr = 0xFFFFu;
        if (i < P) {
            u16 w = wr[i];
            pr = (w != 0xFFFFu) ? g_rank_scores[w] : g_rank_prior[i];
        }
        psr[i] = pr;
    }
    __syncthreads();

    int A = 0;

    if (T > 0) {
        // ---- phase 3a: pool-rank histogram + exclusive prefix (psBelow) ----
        for (int i = tid; i < RMAX; i += nthr) g_hist[i] = 0u;
        __syncthreads();
        for (int i = tid; i < P; i += nthr) atomicAdd(&g_hist[psr[i]], 1u);
        __syncthreads();
        {
            const int CPT = RMAX / 1024;   // 20
            const int base = tid * CPT;
            u32 s = 0;
            #pragma unroll
            for (int j = 0; j < CPT; ++j) s += g_hist[base + j];
            u32 vv = s;
            #pragma unroll
            for (int o = 1; o < 32; o <<= 1) {
                u32 t = __shfl_up_sync(0xFFFFFFFFu, vv, o);
                if (lane >= o) vv += t;
            }
            if (lane == 31) wsum[wid] = (int)vv;
            __syncthreads();
            if (wid == 0) {
                u32 w = (u32)wsum[lane];
                #pragma unroll
                for (int o = 1; o < 32; o <<= 1) {
                    u32 t = __shfl_up_sync(0xFFFFFFFFu, w, o);
                    if (lane >= o) w += t;
                }
                wsum[lane] = (int)w;
            }
            __syncthreads();
            u32 run = (vv - s) + ((wid > 0) ? (u32)wsum[wid - 1] : 0u);
            #pragma unroll
            for (int j = 0; j < CPT; ++j) {
                u32 h = g_hist[base + j];
                g_cursor[base + j] = run;   // psBelow[r] = #pool ranks < r
                run += h;
            }
            __syncthreads();
        }

        // ---- phase 3b: per-warp bitonic sorts of 256-chunks of stream ranks ----
        const int NCH = (T + 255) >> 8;
        for (int i = tid; i < (NCH << 8); i += nthr)
            chunkS[i] = (i < T) ? sr[i] : (u16)0xFFFFu;
        __syncthreads();
        for (int ch = wid; ch < NCH; ch += 32) {
            u16* a = chunkS + (ch << 8);
            for (int k = 2; k <= 256; k <<= 1) {
                for (int j = k >> 1; j > 0; j >>= 1) {
                    for (int idx = lane; idx < 256; idx += 32) {
                        int p = idx ^ j;
                        if (p > idx) {
                            u16 x = a[idx], y = a[p];
                            bool up = ((idx & k) == 0);
                            if (up ? (x > y) : (x < y)) { a[idx] = y; a[p] = x; }
                        }
                    }
                    __syncwarp();
                }
            }
        }
        __syncthreads();

        // ---- phase 3c: cross-chunk below-counts, pair-parallel ----
        for (int q = tid; q < T; q += nthr) Bq[q] = 0u;
        __syncthreads();
        {
            const int pairs = T * NCH;
            for (int idx = tid; idx < pairs; idx += nthr) {
                int q = idx / NCH;
                int c2 = idx - q * NCH;
                if (c2 < (q >> 8)) {
                    int cnt = lb16(chunkS + (c2 << 8), 256, sr[q]);
                    if (cnt) atomicAdd(&Bq[q], (u32)cnt);
                }
            }
        }
        __syncthreads();

        // ---- phase 4: accept decisions + compaction (psb = 1 LDG) ----
        int myCnt = 0;
        u32 amask = 0;
        const int q0 = tid * 16;
        #pragma unroll
        for (int j = 0; j < 16; ++j) {
            int q = q0 + j;
            if (q < T) {
                u16 r = sr[q];
                int b = (int)Bq[q];
                int base = q & ~255;
                for (int jj = base; jj < q; ++jj) b += (sr[jj] < r) ? 1 : 0;
                int psb = (int)g_cursor[r];
                if (psb + b >= q + 1) { amask |= (1u << j); myCnt++; }
            }
        }
        int vv = myCnt;
        #pragma unroll
        for (int o = 1; o < 32; o <<= 1) {
            int t = __shfl_up_sync(0xFFFFFFFFu, vv, o);
            if (lane >= o) vv += t;
        }
        if (lane == 31) wsum[wid] = vv;
        __syncthreads();
        if (wid == 0) {
            int w = wsum[lane];
            #pragma unroll
            for (int o = 1; o < 32; o <<= 1) {
                int t = __shfl_up_sync(0xFFFFFFFFu, w, o);
                if (lane >= o) w += t;
            }
            wsum[lane] = w;
        }
        __syncthreads();
        int jbase = (vv - myCnt) + ((wid > 0) ? wsum[wid - 1] : 0);
        A = wsum[(nthr >> 5) - 1];
        #pragma unroll
        for (int j = 0; j < 16; ++j) {
            if (amask & (1u << j)) {
                int q = q0 + j;
                g_bdata[jbase++] = ((u32)sr[q] << 14) | (u32)si[q];
            }
        }
        __syncthreads();
        // NOTE: buf/sr/si/Bq are DEAD from here (accepted list lives in g_bdata)
    }

    if (A > 0) {
        const int UN = P + A;

        // ---- phase 5: counting sort of U by rank into gU (smem) ----
        // g_hist already holds the pool histogram; add accepted ranks only.
        for (int j = tid; j < A; j += nthr) atomicAdd(&g_hist[g_bdata[j] >> 14], 1u);
        __syncthreads();
        {   // exclusive prefix over RMAX -> g_cursor (U cursors)
            const int CPT = RMAX / 1024;
            const int base = tid * CPT;
            u32 s = 0;
            #pragma unroll
            for (int j = 0; j < CPT; ++j) s += g_hist[base + j];
            u32 vv = s;
            #pragma unroll
            for (int o = 1; o < 32; o <<= 1) {
                u32 t = __shfl_up_sync(0xFFFFFFFFu, vv, o);
                if (lane >= o) vv += t;
            }
            if (lane == 31) wsum[wid] = (int)vv;
            __syncthreads();
            if (wid == 0) {
                u32 w = (u32)wsum[lane];
                #pragma unroll
                for (int o = 1; o < 32; o <<= 1) {
                    u32 t = __shfl_up_sync(0xFFFFFFFFu, w, o);
                    if (lane >= o) w += t;
                }
                wsum[lane] = (int)w;
            }
            __syncthreads();
            u32 run = (vv - s) + ((wid > 0) ? (u32)wsum[wid - 1] : 0u);
            #pragma unroll
            for (int j = 0; j < CPT; ++j) {
                u32 h = g_hist[base + j];
                g_cursor[base + j] = run;
                run += h;
            }
            __syncthreads();
        }
        // scatter: elem = rank<<17 | type<<16 | id
        for (int i = tid; i < P; i += nthr) {
            u32 r = psr[i];
            u32 pos = atomicAdd(&g_cursor[r], 1u);
            gU[pos] = (r << 17) | (u32)i;
        }
        for (int j = tid; j < A; j += nthr) {
            u32 r = g_bdata[j] >> 14;
            u32 pos = atomicAdd(&g_cursor[r], 1u);
            gU[pos] = (r << 17) | 0x10000u | (u32)j;
        }
        __syncthreads();

        // ---- phase 6: tie detection + fixpoint chain resolution (smem) ----
        if (tid == 0) sh_anyTies = 0;
        __syncthreads();
        for (int p = tid; p + 1 < UN; p += nthr)
            if ((gU[p] >> 17) == (gU[p + 1] >> 17)) sh_anyTies = 1;
        __syncthreads();

        const int MAXIT = 32;
        for (int it = 0; it < MAXIT; ++it) {
            // build parents: accept j evicts gU[j]
            for (int j = tid; j < A; j += nthr) {
                u32 e = gU[j];
                par[j] = (e & 0x10000u) ? (e & 0xFFFFu) : (0x80000000u | (e & 0xFFFFu));
            }
            __syncthreads();
            // early-exit pointer jumping
            for (int rd = 0; rd < 15; ++rd) {
                if (tid == 0) sh_changed = 0;
                __syncthreads();
                for (int j = tid; j < A; j += nthr) {
                    u32 pv = par[j];
                    if (!(pv & 0x80000000u)) {
                        u32 g = par[pv];
                        par[j] = g;
                        if (!(g & 0x80000000u)) sh_changed = 1;
                    }
                }
                __syncthreads();
                if (!sh_changed) break;
            }
            if (!sh_anyTies) break;
            if (it == MAXIT - 1) break;
            if (tid == 0) sh_changed = 0;
            __syncthreads();
            // reorder tie groups by (resolved slot, type) — leader per group
            for (int p = tid; p < UN; p += nthr) {
                u32 r = gU[p] >> 17;
                bool leader = (p == 0) || ((gU[p - 1] >> 17) != r);
                if (leader && p + 1 < UN && (gU[p + 1] >> 17) == r) {
                    int len = 1;
                    while (p + len < UN && (gU[p + len] >> 17) == r) len++;
                    bool ch = false;
                    for (int a = 1; a < len; ++a) {
                        u32 x = gU[p + a];
                        u32 sx = (x & 0x10000u) ? (par[x & 0xFFFFu] & 0xFFFFu) : (x & 0xFFFFu);
                        u32 kx = (sx << 1) | ((x >> 16) & 1u);
                        int b = a;
                        while (b > 0) {
                            u32 y = gU[p + b - 1];
                            u32 sy = (y & 0x10000u) ? (par[y & 0xFFFFu] & 0xFFFFu) : (y & 0xFFFFu);
                            u32 ky = (sy << 1) | ((y >> 16) & 1u);
                            if (ky <= kx) break;
                            gU[p + b] = y; b--; ch = true;
                        }
                        gU[p + b] = x;
                    }
                    if (ch) sh_changed = 1;
                }
            }
            __syncthreads();
            if (!sh_changed) break;
        }

        // ---- phase 7: survivors (positions >= A) write the final map ----
        for (int pos = A + tid; pos < UN; pos += nthr) {
            u32 e = gU[pos];
            if (e & 0x10000u) {
                u32 j = e & 0xFFFFu;
                u32 s = par[j] & 0xFFFFu;
                if (s < (u32)P) wr[s] = (u16)(g_bdata[j] & 0x3FFFu);
            }
        }
        __syncthreads();
    }

    // ---- epilogue: writer map out; priorities + count to output tail ----
    const long long obase = (long long)P * (long long)D;
    for (int i = tid; i < P; i += nthr) {
        u16 w = wr[i];
        g_writer[i] = w;
        if (obase + i < out_size)
            out[obase + i] = (w != 0xFFFFu) ? scores[w] : priorities[i];
    }
    if (tid == 0 && obase + P < out_size)
        out[obase + P] = (float)fc;
}

// ---------------------------------------------------------------------------
// Row gather: one block per pool slot.
// ---------------------------------------------------------------------------
__global__ void k_copy(const float* __restrict__ pool,
                       const float* __restrict__ summaries,
                       float* __restrict__ out, int D) {
    const int row = blockIdx.x;
    const u16 w = g_writer[row];
    const float* src = (w == 0xFFFFu) ? (pool + (long long)row * D)
                                      : (summaries + (long long)w * D);
    float* dst = out + (long long)row * D;
    if ((D & 3) == 0) {
        const float4* s4 = (const float4*)src;
        float4* d4 = (float4*)dst;
        for (int i = threadIdx.x; i < (D >> 2); i += blockDim.x) d4[i] = s4[i];
    } else {
        for (int i = threadIdx.x; i < D; i += blockDim.x) dst[i] = src[i];
    }
}

// ---------------------------------------------------------------------------
// Inputs (metadata order): summaries[N,D] f32, scores[N] f32, pool[P,D] f32,
// priorities[P] f32, count i32 scalar.
// Output: concat(pool_out[P*D], priorities[P], count) as f32.
// ---------------------------------------------------------------------------
extern "C" void kernel_launch(void* const* d_in, const int* in_sizes, int n_in,
                              void* d_out, int out_size) {
    const float* summaries  = (const float*)d_in[0];
    const float* scores     = (const float*)d_in[1];
    const float* pool       = (const float*)d_in[2];
    const float* priorities = (const float*)d_in[3];
    const int*   countp     = (const int*)d_in[4];

    const int N = in_sizes[1];
    const int P = in_sizes[3];
    const int D = (N > 0) ? (in_sizes[0] / N) : 0;
    const int M = N + P;
    float* out = (float*)d_out;

    const int fin_smem = SMEM_WORDS * 4;   // 212,992 bytes
    cudaFuncSetAttribute(k_final, cudaFuncAttributeMaxDynamicSharedMemorySize, fin_smem);

    k_zero   <<<NB / 256, 256>>>();
    k_hist   <<<(M + 255) / 256, 256>>>(scores, priorities, N, P);
    k_scan   <<<1, 1024>>>();
    k_scatter<<<(M + 255) / 256, 256>>>(scores, priorities, N, P);
    k_rank   <<<(M + 255) / 256, 256>>>(scores, priorities, N, P);
    k_final  <<<1, 1024, fin_smem>>>(scores, priorities, countp, out,
                                     N, P, D, (long long)out_size);
    k_copy   <<<P, 256>>>(pool, summaries, out, D);
}

// round 10
// speedup vs baseline: 12.8104x; 4.3910x over previous
#include <cuda_runtime.h>
#include <cstdint>

// Problem constants (upper bounds; runtime shapes read from in_sizes)
#define NMAX 16384
#define PMAX 4096
#define NB   16384              // rank buckets for the ranking pipeline
#define RMAX (NMAX + PMAX)      // 20480 distinct ranks max

typedef unsigned int u32;
typedef unsigned short u16;

// -------- cross-kernel scratch (allocation-free: __device__ globals) --------
__device__ u16 g_writer[PMAX];        // last writer item per slot, 0xFFFF = keep original
__device__ u32 g_hist[RMAX];          // rank-pipeline hist (NB) / pool+U rank hist (RMAX)
__device__ u32 g_prefix[NB];          // rank-pipeline prefix
__device__ u32 g_cursor[RMAX];        // rank-pipeline cursors / psBelow / U cursors
__device__ u32 g_bdata[RMAX];         // rank-pipeline bucket data; later accList
__device__ u16 g_rank_scores[NMAX];   // exact rank of each score
__device__ u16 g_rank_prior[PMAX];    // exact rank of each input priority
__device__ u16 g_sr[NMAX];            // stream ranks
__device__ u16 g_si[NMAX];            // stream item ids
__device__ u16 g_chunkS[NMAX];        // per-256-chunk sorted stream ranks
__device__ u16 g_psr[PMAX];           // poolstart ranks
__device__ u32 g_Bq[NMAX];            // dominance counts
__device__ int g_T, g_A, g_fc;

// order-preserving u32 transform of float (total order matching IEEE <)
__device__ __forceinline__ u32 okey(float v) {
    u32 b = __float_as_uint(v);
    return (b & 0x80000000u) ? ~b : (b | 0x80000000u);
}
// monotone bucketing (exactness NOT required; monotone + equal-on-equal is)
__device__ __forceinline__ int bucketOf(float v) {
    if (!(v > 0.0f)) return 0;
    if (v >= 1.0f)   return NB - 1;
    int b = (int)(v * 16384.0f);
    return b < 0 ? 0 : (b > NB - 1 ? NB - 1 : b);
}

// ---------------------------------------------------------------------------
// Rank pipeline: hist -> scan -> scatter -> rank  (NB shrunk to 16384)
// ---------------------------------------------------------------------------
__global__ void k_zero() {
    int i = blockIdx.x * blockDim.x + threadIdx.x;
    if (i < NB) g_hist[i] = 0u;
}

__global__ void k_hist(const float* __restrict__ scores,
                       const float* __restrict__ priorities, int N, int P) {
    int i = blockIdx.x * blockDim.x + threadIdx.x;
    if (i >= N + P) return;
    float v = (i < N) ? scores[i] : priorities[i - N];
    atomicAdd(&g_hist[bucketOf(v)], 1u);
}

__global__ __launch_bounds__(1024, 1) void k_scan() {
    __shared__ u32 wsum[32];
    const int tid = threadIdx.x;
    const int CPT = NB / 1024;            // 16
    const int base = tid * CPT;
    u32 s = 0;
    #pragma unroll 8
    for (int j = 0; j < CPT; ++j) s += g_hist[base + j];

    const int lane = tid & 31, wid = tid >> 5;
    u32 v = s;
    #pragma unroll
    for (int o = 1; o < 32; o <<= 1) {
        u32 t = __shfl_up_sync(0xFFFFFFFFu, v, o);
        if (lane >= o) v += t;
    }
    if (lane == 31) wsum[wid] = v;
    __syncthreads();
    if (wid == 0) {
        u32 w = wsum[lane];
        #pragma unroll
        for (int o = 1; o < 32; o <<= 1) {
            u32 t = __shfl_up_sync(0xFFFFFFFFu, w, o);
            if (lane >= o) w += t;
        }
        wsum[lane] = w;
    }
    __syncthreads();
    u32 run = (v - s) + ((wid > 0) ? wsum[wid - 1] : 0u);
    #pragma unroll 8
    for (int j = 0; j < CPT; ++j) {
        u32 h = g_hist[base + j];
        g_prefix[base + j] = run;
        g_cursor[base + j] = run;
        run += h;
    }
}

__global__ void k_scatter(const float* __restrict__ scores,
                          const float* __restrict__ priorities, int N, int P) {
    int i = blockIdx.x * blockDim.x + threadIdx.x;
    if (i >= N + P) return;
    float v = (i < N) ? scores[i] : priorities[i - N];
    u32 pos = atomicAdd(&g_cursor[bucketOf(v)], 1u);
    g_bdata[pos] = okey(v);
}

__global__ void k_rank(const float* __restrict__ scores,
                       const float* __restrict__ priorities, int N, int P) {
    int i = blockIdx.x * blockDim.x + threadIdx.x;
    if (i >= N + P) return;
    float v = (i < N) ? scores[i] : priorities[i - N];
    u16 r;
    if (!(v > 0.0f)) {
        r = 0;
    } else {
        int b = bucketOf(v);
        u32 k = okey(v);
        u32 base = g_prefix[b];
        u32 n = g_hist[b];
        u32 c = 0;
        for (u32 j = 0; j < n; ++j) c += (g_bdata[base + j] < k) ? 1u : 0u;
        r = (u16)(base + c);
    }
    if (i < N) g_rank_scores[i] = r; else g_rank_prior[i - N] = r;
}

// ---------------------------------------------------------------------------
// k_classify (single block): classify + stream arrays + poolstart ranks +
// pool-rank histogram + psBelow prefix.
// ---------------------------------------------------------------------------
__global__ __launch_bounds__(1024, 1)
void k_classify(const float* __restrict__ scores, const int* __restrict__ countp,
                int N, int P) {
    extern __shared__ u32 S[];
    u32* sbits = S;                        // NMAX
    u16* wr    = (u16*)(S + NMAX);         // PMAX
    __shared__ int wsum[32];

    const int tid = threadIdx.x;
    const int nthr = blockDim.x;
    const int lane = tid & 31, wid = tid >> 5;

    for (int i = tid; i < NMAX; i += nthr)
        sbits[i] = (i < N) ? __float_as_uint(scores[i]) : 0u;
    for (int i = tid; i < PMAX; i += nthr) wr[i] = 0xFFFFu;
    __syncthreads();

    const int C0 = *countp;
    const int CH = NMAX / 1024;            // 16
    const int start = tid * CH;
    int c = 0;
    #pragma unroll
    for (int j = 0; j < CH; ++j)
        c += (__uint_as_float(sbits[start + j]) > 0.5f) ? 1 : 0;

    int v = c;
    #pragma unroll
    for (int o = 1; o < 32; o <<= 1) {
        int t = __shfl_up_sync(0xFFFFFFFFu, v, o);
        if (lane >= o) v += t;
    }
    if (lane == 31) wsum[wid] = v;
    __syncthreads();
    if (wid == 0) {
        int w = wsum[lane];
        #pragma unroll
        for (int o = 1; o < 32; o <<= 1) {
            int t = __shfl_up_sync(0xFFFFFFFFu, w, o);
            if (lane >= o) w += t;
        }
        wsum[lane] = w;
    }
    __syncthreads();
    const int excl = (v - c) + ((wid > 0) ? wsum[wid - 1] : 0);
    const int total = wsum[(nthr >> 5) - 1];
    int room = P - C0; if (room < 0) room = 0;
    const int T  = (total > room) ? total - room : 0;
    const int fc = C0 + ((total < room) ? total : room);
    {
        int r = excl;
        #pragma unroll
        for (int j = 0; j < CH; ++j) {
            int i = start + j;
            if (__uint_as_float(sbits[i]) > 0.5f) {
                if (r < room) wr[C0 + r] = (u16)i;
                else          g_si[r - room] = (u16)i;
                r++;
            }
        }
    }
    if (tid == 0) { g_T = T; g_fc = fc; }
    __syncthreads();

    // stream ranks
    for (int q = tid; q < T; q += nthr) g_sr[q] = g_rank_scores[g_si[q]];

    // poolstart ranks + writer map to global; pool-rank histogram
    for (int i = tid; i < RMAX; i += nthr) g_hist[i] = 0u;
    __syncthreads();
    for (int i = tid; i < P; i += nthr) {
        u16 w = wr[i];
        u16 pr = (w != 0xFFFFu) ? g_rank_scores[w] : g_rank_prior[i];
        g_psr[i] = pr;
        g_writer[i] = w;
        atomicAdd(&g_hist[pr], 1u);
    }
    __syncthreads();
    {   // exclusive prefix over RMAX -> g_cursor (psBelow[r] = #pool ranks < r)
        const int CPT = RMAX / 1024;       // 20
        const int base = tid * CPT;
        u32 s = 0;
        #pragma unroll
        for (int j = 0; j < CPT; ++j) s += g_hist[base + j];
        u32 vv = s;
        #pragma unroll
        for (int o = 1; o < 32; o <<= 1) {
            u32 t = __shfl_up_sync(0xFFFFFFFFu, vv, o);
            if (lane >= o) vv += t;
        }
        if (lane == 31) wsum[wid] = (int)vv;
        __syncthreads();
        if (wid == 0) {
            u32 w = (u32)wsum[lane];
            #pragma unroll
            for (int o = 1; o < 32; o <<= 1) {
                u32 t = __shfl_up_sync(0xFFFFFFFFu, w, o);
                if (lane >= o) w += t;
            }
            wsum[lane] = (int)w;
        }
        __syncthreads();
        u32 run = (vv - s) + ((wid > 0) ? (u32)wsum[wid - 1] : 0u);
        #pragma unroll
        for (int j = 0; j < CPT; ++j) {
            u32 h = g_hist[base + j];
            g_cursor[base + j] = run;
            run += h;
        }
    }
}

// ---------------------------------------------------------------------------
// k_chunksort: one block per 256-chunk, bitonic sort of stream ranks.
// ---------------------------------------------------------------------------
__global__ __launch_bounds__(256, 4)
void k_chunksort() {
    __shared__ u16 a[256];
    const int T = g_T;
    const int tid = threadIdx.x;
    const int i = (blockIdx.x << 8) + tid;
    a[tid] = (i < T) ? g_sr[i] : (u16)0xFFFFu;
    __syncthreads();
    for (int k = 2; k <= 256; k <<= 1) {
        for (int j = k >> 1; j > 0; j >>= 1) {
            int p = tid ^ j;
            if (p > tid) {
                u16 x = a[tid], y = a[p];
                bool up = ((tid & k) == 0);
                if (up ? (x > y) : (x < y)) { a[tid] = y; a[p] = x; }
            }
            __syncthreads();
        }
    }
    g_chunkS[i] = a[tid];
}

// ---------------------------------------------------------------------------
// k_count: grid-wide dominance counts. One warp per stream item:
//   B(q) = sum over full chunks < chunk(q) of lb(chunkS, r_q)
//        + #{j in same chunk, j<q : r_j < r_q}
// ---------------------------------------------------------------------------
__global__ __launch_bounds__(256, 8)
void k_count() {
    const int T = g_T;
    if (T <= 0) return;
    const int lane = threadIdx.x & 31;
    const int warpsTotal = (gridDim.x * blockDim.x) >> 5;
    const int gw = ((blockIdx.x * blockDim.x + threadIdx.x) >> 5);

    for (int q = gw; q < T; q += warpsTotal) {
        const u16 r = g_sr[q];
        const int c0 = q >> 8;
        u32 cnt = 0;
        // full earlier chunks: binary search each (lanes strided)
        for (int ch = lane; ch < c0; ch += 32) {
            const u16* a = g_chunkS + (ch << 8);
            int lo = 0, hi = 256;
            while (lo < hi) { int m = (lo + hi) >> 1; if (a[m] < r) lo = m + 1; else hi = m; }
            cnt += (u32)lo;
        }
        // same-chunk preceding elements
        for (int j = (q & ~255) + lane; j < q; j += 32)
            cnt += (g_sr[j] < r) ? 1u : 0u;
        #pragma unroll
        for (int o = 16; o; o >>= 1) cnt += __shfl_down_sync(0xFFFFFFFFu, cnt, o);
        if (lane == 0) g_Bq[q] = cnt;
    }
}

// ---------------------------------------------------------------------------
// k_accept (single block): accept(q) <=> psBelow[r_q] + B(q) >= q+1 ;
// ordered compaction of accepted (rank<<14|item) into g_bdata; A -> g_A.
// ---------------------------------------------------------------------------
__global__ __launch_bounds__(1024, 1)
void k_accept() {
    __shared__ int wsum[32];
    const int tid = threadIdx.x;
    const int lane = tid & 31, wid = tid >> 5;
    const int T = g_T;

    int myCnt = 0;
    u32 amask = 0;
    const int q0 = tid * 16;
    u16 rs[16];
    #pragma unroll
    for (int j = 0; j < 16; ++j) {
        int q = q0 + j;
        if (q < T) {
            u16 r = g_sr[q];
            rs[j] = r;
            int b = (int)g_Bq[q];
            int psb = (int)g_cursor[r];
            if (psb + b >= q + 1) { amask |= (1u << j); myCnt++; }
        }
    }
    int vv = myCnt;
    #pragma unroll
    for (int o = 1; o < 32; o <<= 1) {
        int t = __shfl_up_sync(0xFFFFFFFFu, vv, o);
        if (lane >= o) vv += t;
    }
    if (lane == 31) wsum[wid] = vv;
    __syncthreads();
    if (wid == 0) {
        int w = wsum[lane];
        #pragma unroll
        for (int o = 1; o < 32; o <<= 1) {
            int t = __shfl_up_sync(0xFFFFFFFFu, w, o);
            if (lane >= o) w += t;
        }
        wsum[lane] = w;
    }
    __syncthreads();
    int jbase = (vv - myCnt) + ((wid > 0) ? wsum[wid - 1] : 0);
    if (tid == 0) g_A = wsum[(blockDim.x >> 5) - 1];
    #pragma unroll
    for (int j = 0; j < 16; ++j) {
        if (amask & (1u << j)) {
            int q = q0 + j;
            g_bdata[jbase++] = ((u32)rs[j] << 14) | (u32)g_si[q];
        }
    }
}

// ---------------------------------------------------------------------------
// k_resolve (single block): counting sort of U = poolstart ∪ accepted by rank
// into smem gU; accept j evicts gU[j]; slot chains via early-exit pointer
// jumping; intra-rank tie fixpoint by slot; survivors -> writer map; epilogue.
// (Logic identical to the R8-verified phases 5-7.)
// ---------------------------------------------------------------------------
__global__ __launch_bounds__(1024, 1)
void k_resolve(const float* __restrict__ scores,
               const float* __restrict__ priorities,
               float* __restrict__ out,
               int P, int D, long long out_size) {
    extern __shared__ u32 S[];
    u32* gU  = S;                          // RMAX
    u32* par = S + RMAX;                   // NMAX
    u16* wr  = (u16*)(S + RMAX + NMAX);    // PMAX
    __shared__ int wsum[32];
    __shared__ int sh_changed, sh_anyTies;

    const int tid = threadIdx.x;
    const int nthr = blockDim.x;
    const int lane = tid & 31, wid = tid >> 5;
    const int A = g_A;

    for (int i = tid; i < PMAX; i += nthr) wr[i] = (i < P) ? g_writer[i] : (u16)0xFFFFu;
    __syncthreads();

    if (A > 0) {
        const int UN = P + A;

        // add accepted ranks to the pool histogram (g_hist preserved)
        for (int j = tid; j < A; j += nthr) atomicAdd(&g_hist[g_bdata[j] >> 14], 1u);
        __syncthreads();
        {   // exclusive prefix over RMAX -> g_cursor (U cursors)
            const int CPT = RMAX / 1024;
            const int base = tid * CPT;
            u32 s = 0;
            #pragma unroll
            for (int j = 0; j < CPT; ++j) s += g_hist[base + j];
            u32 vv = s;
            #pragma unroll
            for (int o = 1; o < 32; o <<= 1) {
                u32 t = __shfl_up_sync(0xFFFFFFFFu, vv, o);
                if (lane >= o) vv += t;
            }
            if (lane == 31) wsum[wid] = (int)vv;
            __syncthreads();
            if (wid == 0) {
                u32 w = (u32)wsum[lane];
                #pragma unroll
                for (int o = 1; o < 32; o <<= 1) {
                    u32 t = __shfl_up_sync(0xFFFFFFFFu, w, o);
                    if (lane >= o) w += t;
                }
                wsum[lane] = (int)w;
            }
            __syncthreads();
            u32 run = (vv - s) + ((wid > 0) ? (u32)wsum[wid - 1] : 0u);
            #pragma unroll
            for (int j = 0; j < CPT; ++j) {
                u32 h = g_hist[base + j];
                g_cursor[base + j] = run;
                run += h;
            }
            __syncthreads();
        }
        // scatter: elem = rank<<17 | type<<16 | id
        for (int i = tid; i < P; i += nthr) {
            u32 r = (u32)g_psr[i];
            u32 pos = atomicAdd(&g_cursor[r], 1u);
            gU[pos] = (r << 17) | (u32)i;
        }
        for (int j = tid; j < A; j += nthr) {
            u32 r = g_bdata[j] >> 14;
            u32 pos = atomicAdd(&g_cursor[r], 1u);
            gU[pos] = (r << 17) | 0x10000u | (u32)j;
        }
        __syncthreads();

        // tie detection
        if (tid == 0) sh_anyTies = 0;
        __syncthreads();
        for (int p = tid; p + 1 < UN; p += nthr)
            if ((gU[p] >> 17) == (gU[p + 1] >> 17)) sh_anyTies = 1;
        __syncthreads();

        const int MAXIT = 32;
        for (int it = 0; it < MAXIT; ++it) {
            for (int j = tid; j < A; j += nthr) {
                u32 e = gU[j];
                par[j] = (e & 0x10000u) ? (e & 0xFFFFu) : (0x80000000u | (e & 0xFFFFu));
            }
            __syncthreads();
            for (int rd = 0; rd < 15; ++rd) {
                if (tid == 0) sh_changed = 0;
                __syncthreads();
                for (int j = tid; j < A; j += nthr) {
                    u32 pv = par[j];
                    if (!(pv & 0x80000000u)) {
                        u32 g = par[pv];
                        par[j] = g;
                        if (!(g & 0x80000000u)) sh_changed = 1;
                    }
                }
                __syncthreads();
                if (!sh_changed) break;
            }
            if (!sh_anyTies) break;
            if (it == MAXIT - 1) break;
            if (tid == 0) sh_changed = 0;
            __syncthreads();
            for (int p = tid; p < UN; p += nthr) {
                u32 r = gU[p] >> 17;
                bool leader = (p == 0) || ((gU[p - 1] >> 17) != r);
                if (leader && p + 1 < UN && (gU[p + 1] >> 17) == r) {
                    int len = 1;
                    while (p + len < UN && (gU[p + len] >> 17) == r) len++;
                    bool ch = false;
                    for (int a = 1; a < len; ++a) {
                        u32 x = gU[p + a];
                        u32 sx = (x & 0x10000u) ? (par[x & 0xFFFFu] & 0xFFFFu) : (x & 0xFFFFu);
                        u32 kx = (sx << 1) | ((x >> 16) & 1u);
                        int b = a;
                        while (b > 0) {
                            u32 y = gU[p + b - 1];
                            u32 sy = (y & 0x10000u) ? (par[y & 0xFFFFu] & 0xFFFFu) : (y & 0xFFFFu);
                            u32 ky = (sy << 1) | ((y >> 16) & 1u);
                            if (ky <= kx) break;
                            gU[p + b] = y; b--; ch = true;
                        }
                        gU[p + b] = x;
                    }
                    if (ch) sh_changed = 1;
                }
            }
            __syncthreads();
            if (!sh_changed) break;
        }

        // survivors (positions >= A) write the final map
        for (int pos = A + tid; pos < UN; pos += nthr) {
            u32 e = gU[pos];
            if (e & 0x10000u) {
                u32 j = e & 0xFFFFu;
                u32 s = par[j] & 0xFFFFu;
                if (s < (u32)P) wr[s] = (u16)(g_bdata[j] & 0x3FFFu);
            }
        }
        __syncthreads();
    }

    // epilogue
    const long long obase = (long long)P * (long long)D;
    for (int i = tid; i < P; i += nthr) {
        u16 w = wr[i];
        g_writer[i] = w;
        if (obase + i < out_size)
            out[obase + i] = (w != 0xFFFFu) ? scores[w] : priorities[i];
    }
    if (tid == 0 && obase + P < out_size)
        out[obase + P] = (float)g_fc;
}

// ---------------------------------------------------------------------------
// Row gather: one block per pool slot.
// ---------------------------------------------------------------------------
__global__ void k_copy(const float* __restrict__ pool,
                       const float* __restrict__ summaries,
                       float* __restrict__ out, int D) {
    const int row = blockIdx.x;
    const u16 w = g_writer[row];
    const float* src = (w == 0xFFFFu) ? (pool + (long long)row * D)
                                      : (summaries + (long long)w * D);
    float* dst = out + (long long)row * D;
    if ((D & 3) == 0) {
        const float4* s4 = (const float4*)src;
        float4* d4 = (float4*)dst;
        for (int i = threadIdx.x; i < (D >> 2); i += blockDim.x) d4[i] = s4[i];
    } else {
        for (int i = threadIdx.x; i < D; i += blockDim.x) dst[i] = src[i];
    }
}

// ---------------------------------------------------------------------------
// Inputs (metadata order): summaries[N,D] f32, scores[N] f32, pool[P,D] f32,
// priorities[P] f32, count i32 scalar.
// Output: concat(pool_out[P*D], priorities[P], count) as f32.
// ---------------------------------------------------------------------------
extern "C" void kernel_launch(void* const* d_in, const int* in_sizes, int n_in,
                              void* d_out, int out_size) {
    const float* summaries  = (const float*)d_in[0];
    const float* scores     = (const float*)d_in[1];
    const float* pool       = (const float*)d_in[2];
    const float* priorities = (const float*)d_in[3];
    const int*   countp     = (const int*)d_in[4];

    const int N = in_sizes[1];
    const int P = in_sizes[3];
    const int D = (N > 0) ? (in_sizes[0] / N) : 0;
    const int M = N + P;
    float* out = (float*)d_out;

    const int cls_smem = NMAX * 4 + PMAX * 2;            // 73,728
    const int res_smem = (RMAX + NMAX) * 4 + PMAX * 2;   // 155,648
    cudaFuncSetAttribute(k_classify, cudaFuncAttributeMaxDynamicSharedMemorySize, cls_smem);
    cudaFuncSetAttribute(k_resolve,  cudaFuncAttributeMaxDynamicSharedMemorySize, res_smem);

    k_zero     <<<NB / 256, 256>>>();
    k_hist     <<<(M + 255) / 256, 256>>>(scores, priorities, N, P);
    k_scan     <<<1, 1024>>>();
    k_scatter  <<<(M + 255) / 256, 256>>>(scores, priorities, N, P);
    k_rank     <<<(M + 255) / 256, 256>>>(scores, priorities, N, P);
    k_classify <<<1, 1024, cls_smem>>>(scores, countp, N, P);
    k_chunksort<<<NMAX / 256, 256>>>();
    k_count    <<<512, 256>>>();
    k_accept   <<<1, 1024>>>();
    k_resolve  <<<1, 1024, res_smem>>>(scores, priorities, out, P, D, (long long)out_size);
    k_copy     <<<P, 256>>>(pool, summaries, out, D);
}

// round 11
// speedup vs baseline: 13.0790x; 1.0210x over previous
#include <cuda_runtime.h>
#include <cstdint>

// Problem constants (upper bounds; runtime shapes read from in_sizes)
#define NMAX 16384
#define PMAX 4096
#define NB   16384              // rank buckets for the ranking pipeline
#define RMAX (NMAX + PMAX)      // 20480 distinct ranks max

typedef unsigned int u32;
typedef unsigned short u16;

// -------- cross-kernel scratch (allocation-free: __device__ globals) --------
// INVARIANT: g_hist is all-zero at kernel_launch entry. It is zero-initialized
// at module load, and k_resolve re-zeroes it at the end of every run.
__device__ u16 g_writer[PMAX];        // last writer item per slot, 0xFFFF = keep original
__device__ u32 g_hist[RMAX];          // rank-pipeline hist (NB) / pool+U rank hist (RMAX)
__device__ u32 g_prefix[NB];          // rank-pipeline prefix
__device__ u32 g_cursor[RMAX];        // rank-pipeline cursors / psBelow / U cursors
__device__ u32 g_bdata[RMAX];         // rank-pipeline bucket data; later accList
__device__ u16 g_rank_scores[NMAX];   // exact rank of each score
__device__ u16 g_rank_prior[PMAX];    // exact rank of each input priority
__device__ u16 g_sr[NMAX];            // stream ranks
__device__ u16 g_si[NMAX];            // stream item ids
__device__ u16 g_chunkS[NMAX];        // per-256-chunk sorted stream ranks
__device__ u16 g_psr[PMAX];           // poolstart ranks
__device__ u32 g_Bq[NMAX];            // dominance counts
__device__ int g_T, g_fc;

// order-preserving u32 transform of float (total order matching IEEE <)
__device__ __forceinline__ u32 okey(float v) {
    u32 b = __float_as_uint(v);
    return (b & 0x80000000u) ? ~b : (b | 0x80000000u);
}
// monotone bucketing (exactness NOT required; monotone + equal-on-equal is)
__device__ __forceinline__ int bucketOf(float v) {
    if (!(v > 0.0f)) return 0;
    if (v >= 1.0f)   return NB - 1;
    int b = (int)(v * 16384.0f);
    return b < 0 ? 0 : (b > NB - 1 ? NB - 1 : b);
}

// ---------------------------------------------------------------------------
// Rank pipeline: hist -> scan -> scatter -> rank
// (g_hist is pre-zeroed by the invariant above; no k_zero kernel)
// ---------------------------------------------------------------------------
__global__ void k_hist(const float* __restrict__ scores,
                       const float* __restrict__ priorities, int N, int P) {
    int i = blockIdx.x * blockDim.x + threadIdx.x;
    if (i >= N + P) return;
    float v = (i < N) ? scores[i] : priorities[i - N];
    atomicAdd(&g_hist[bucketOf(v)], 1u);
}

__global__ __launch_bounds__(1024, 1) void k_scan() {
    __shared__ u32 wsum[32];
    const int tid = threadIdx.x;
    const int CPT = NB / 1024;            // 16
    const int base = tid * CPT;
    u32 s = 0;
    #pragma unroll 8
    for (int j = 0; j < CPT; ++j) s += g_hist[base + j];

    const int lane = tid & 31, wid = tid >> 5;
    u32 v = s;
    #pragma unroll
    for (int o = 1; o < 32; o <<= 1) {
        u32 t = __shfl_up_sync(0xFFFFFFFFu, v, o);
        if (lane >= o) v += t;
    }
    if (lane == 31) wsum[wid] = v;
    __syncthreads();
    if (wid == 0) {
        u32 w = wsum[lane];
        #pragma unroll
        for (int o = 1; o < 32; o <<= 1) {
            u32 t = __shfl_up_sync(0xFFFFFFFFu, w, o);
            if (lane >= o) w += t;
        }
        wsum[lane] = w;
    }
    __syncthreads();
    u32 run = (v - s) + ((wid > 0) ? wsum[wid - 1] : 0u);
    #pragma unroll 8
    for (int j = 0; j < CPT; ++j) {
        u32 h = g_hist[base + j];
        g_prefix[base + j] = run;
        g_cursor[base + j] = run;
        run += h;
    }
}

__global__ void k_scatter(const float* __restrict__ scores,
                          const float* __restrict__ priorities, int N, int P) {
    int i = blockIdx.x * blockDim.x + threadIdx.x;
    if (i >= N + P) return;
    float v = (i < N) ? scores[i] : priorities[i - N];
    u32 pos = atomicAdd(&g_cursor[bucketOf(v)], 1u);
    g_bdata[pos] = okey(v);
}

__global__ void k_rank(const float* __restrict__ scores,
                       const float* __restrict__ priorities, int N, int P) {
    int i = blockIdx.x * blockDim.x + threadIdx.x;
    if (i >= N + P) return;
    float v = (i < N) ? scores[i] : priorities[i - N];
    u16 r;
    if (!(v > 0.0f)) {
        r = 0;
    } else {
        int b = bucketOf(v);
        u32 k = okey(v);
        u32 base = g_prefix[b];
        u32 n = g_hist[b];
        u32 c = 0;
        for (u32 j = 0; j < n; ++j) c += (g_bdata[base + j] < k) ? 1u : 0u;
        r = (u16)(base + c);
    }
    if (i < N) g_rank_scores[i] = r; else g_rank_prior[i - N] = r;
}

// ---------------------------------------------------------------------------
// k_classify (single block): classify + stream arrays + poolstart ranks +
// pool-rank histogram + psBelow prefix.
// ---------------------------------------------------------------------------
__global__ __launch_bounds__(1024, 1)
void k_classify(const float* __restrict__ scores, const int* __restrict__ countp,
                int N, int P) {
    extern __shared__ u32 S[];
    u32* sbits = S;                        // NMAX
    u16* wr    = (u16*)(S + NMAX);         // PMAX
    __shared__ int wsum[32];

    const int tid = threadIdx.x;
    const int nthr = blockDim.x;
    const int lane = tid & 31, wid = tid >> 5;

    // vectorized score staging (float4)
    for (int i4 = tid; i4 < NMAX / 4; i4 += nthr) {
        int i = i4 * 4;
        uint4 v;
        if (i + 3 < N) {
            v = *reinterpret_cast<const uint4*>(scores + i);
        } else {
            v.x = (i + 0 < N) ? __float_as_uint(scores[i + 0]) : 0u;
            v.y = (i + 1 < N) ? __float_as_uint(scores[i + 1]) : 0u;
            v.z = (i + 2 < N) ? __float_as_uint(scores[i + 2]) : 0u;
            v.w = (i + 3 < N) ? __float_as_uint(scores[i + 3]) : 0u;
        }
        *reinterpret_cast<uint4*>(sbits + i) = v;
    }
    for (int i = tid; i < PMAX; i += nthr) wr[i] = 0xFFFFu;
    __syncthreads();

    const int C0 = *countp;
    const int CH = NMAX / 1024;            // 16
    const int start = tid * CH;
    int c = 0;
    #pragma unroll
    for (int j = 0; j < CH; ++j)
        c += (__uint_as_float(sbits[start + j]) > 0.5f) ? 1 : 0;

    int v = c;
    #pragma unroll
    for (int o = 1; o < 32; o <<= 1) {
        int t = __shfl_up_sync(0xFFFFFFFFu, v, o);
        if (lane >= o) v += t;
    }
    if (lane == 31) wsum[wid] = v;
    __syncthreads();
    if (wid == 0) {
        int w = wsum[lane];
        #pragma unroll
        for (int o = 1; o < 32; o <<= 1) {
            int t = __shfl_up_sync(0xFFFFFFFFu, w, o);
            if (lane >= o) w += t;
        }
        wsum[lane] = w;
    }
    __syncthreads();
    const int excl = (v - c) + ((wid > 0) ? wsum[wid - 1] : 0);
    const int total = wsum[(nthr >> 5) - 1];
    int room = P - C0; if (room < 0) room = 0;
    const int T  = (total > room) ? total - room : 0;
    const int fc = C0 + ((total < room) ? total : room);
    {
        int r = excl;
        #pragma unroll
        for (int j = 0; j < CH; ++j) {
            int i = start + j;
            if (__uint_as_float(sbits[i]) > 0.5f) {
                if (r < room) wr[C0 + r] = (u16)i;
                else          g_si[r - room] = (u16)i;
                r++;
            }
        }
    }
    if (tid == 0) { g_T = T; g_fc = fc; }
    __syncthreads();

    // stream ranks
    for (int q = tid; q < T; q += nthr) g_sr[q] = g_rank_scores[g_si[q]];

    // poolstart ranks + writer map to global; pool-rank histogram
    for (int i = tid; i < RMAX; i += nthr) g_hist[i] = 0u;
    __syncthreads();
    for (int i = tid; i < P; i += nthr) {
        u16 w = wr[i];
        u16 pr = (w != 0xFFFFu) ? g_rank_scores[w] : g_rank_prior[i];
        g_psr[i] = pr;
        g_writer[i] = w;
        atomicAdd(&g_hist[pr], 1u);
    }
    __syncthreads();
    {   // exclusive prefix over RMAX -> g_cursor (psBelow[r] = #pool ranks < r)
        const int CPT = RMAX / 1024;       // 20
        const int base = tid * CPT;
        u32 s = 0;
        #pragma unroll
        for (int j = 0; j < CPT; ++j) s += g_hist[base + j];
        u32 vv = s;
        #pragma unroll
        for (int o = 1; o < 32; o <<= 1) {
            u32 t = __shfl_up_sync(0xFFFFFFFFu, vv, o);
            if (lane >= o) vv += t;
        }
        if (lane == 31) wsum[wid] = (int)vv;
        __syncthreads();
        if (wid == 0) {
            u32 w = (u32)wsum[lane];
            #pragma unroll
            for (int o = 1; o < 32; o <<= 1) {
                u32 t = __shfl_up_sync(0xFFFFFFFFu, w, o);
                if (lane >= o) w += t;
            }
            wsum[lane] = (int)w;
        }
        __syncthreads();
        u32 run = (vv - s) + ((wid > 0) ? (u32)wsum[wid - 1] : 0u);
        #pragma unroll
        for (int j = 0; j < CPT; ++j) {
            u32 h = g_hist[base + j];
            g_cursor[base + j] = run;
            run += h;
        }
    }
}

// ---------------------------------------------------------------------------
// k_chunksort: one block per 256-chunk, bitonic sort of stream ranks.
// ---------------------------------------------------------------------------
__global__ __launch_bounds__(256, 4)
void k_chunksort() {
    __shared__ u16 a[256];
    const int T = g_T;
    const int tid = threadIdx.x;
    const int i = (blockIdx.x << 8) + tid;
    a[tid] = (i < T) ? g_sr[i] : (u16)0xFFFFu;
    __syncthreads();
    for (int k = 2; k <= 256; k <<= 1) {
        for (int j = k >> 1; j > 0; j >>= 1) {
            int p = tid ^ j;
            if (p > tid) {
                u16 x = a[tid], y = a[p];
                bool up = ((tid & k) == 0);
                if (up ? (x > y) : (x < y)) { a[tid] = y; a[p] = x; }
            }
            __syncthreads();
        }
    }
    g_chunkS[i] = a[tid];
}

// ---------------------------------------------------------------------------
// k_count: grid-wide dominance counts. One warp per stream item:
//   B(q) = sum over full chunks < chunk(q) of lb(chunkS, r_q)
//        + #{j in same chunk, j<q : r_j < r_q}
// ---------------------------------------------------------------------------
__global__ __launch_bounds__(256, 8)
void k_count() {
    const int T = g_T;
    if (T <= 0) return;
    const int lane = threadIdx.x & 31;
    const int warpsTotal = (gridDim.x * blockDim.x) >> 5;
    const int gw = ((blockIdx.x * blockDim.x + threadIdx.x) >> 5);

    for (int q = gw; q < T; q += warpsTotal) {
        const u16 r = g_sr[q];
        const int c0 = q >> 8;
        u32 cnt = 0;
        for (int ch = lane; ch < c0; ch += 32) {
            const u16* a = g_chunkS + (ch << 8);
            int lo = 0, hi = 256;
            while (lo < hi) { int m = (lo + hi) >> 1; if (a[m] < r) lo = m + 1; else hi = m; }
            cnt += (u32)lo;
        }
        for (int j = (q & ~255) + lane; j < q; j += 32)
            cnt += (g_sr[j] < r) ? 1u : 0u;
        #pragma unroll
        for (int o = 16; o; o >>= 1) cnt += __shfl_down_sync(0xFFFFFFFFu, cnt, o);
        if (lane == 0) g_Bq[q] = cnt;
    }
}

// ---------------------------------------------------------------------------
// k_resolve (single block): FUSED accept + resolve + epilogue + hist re-zero.
//  accept(q) <=> psBelow[r_q] + B(q) >= q+1 ; ordered compaction -> g_bdata.
//  Then: counting sort of U = poolstart ∪ accepted by rank into smem gU;
//  accept j evicts gU[j]; slot chains via early-exit pointer jumping; intra-
//  rank tie fixpoint by slot; survivors -> writer map; epilogue; zero g_hist.
// ---------------------------------------------------------------------------
__global__ __launch_bounds__(1024, 1)
void k_resolve(const float* __restrict__ scores,
               const float* __restrict__ priorities,
               float* __restrict__ out,
               int P, int D, long long out_size) {
    extern __shared__ u32 S[];
    u32* gU  = S;                          // RMAX
    u32* par = S + RMAX;                   // NMAX
    u16* wr  = (u16*)(S + RMAX + NMAX);    // PMAX
    __shared__ int wsum[32];
    __shared__ int sh_changed, sh_anyTies, sh_A;

    const int tid = threadIdx.x;
    const int nthr = blockDim.x;
    const int lane = tid & 31, wid = tid >> 5;
    const int T = g_T;

    // ---- accept phase (formerly k_accept) ----
    {
        int myCnt = 0;
        u32 amask = 0;
        const int q0 = tid * 16;
        u16 rs[16];
        #pragma unroll
        for (int j = 0; j < 16; ++j) {
            int q = q0 + j;
            if (q < T) {
                u16 r = g_sr[q];
                rs[j] = r;
                int b = (int)g_Bq[q];
                int psb = (int)g_cursor[r];
                if (psb + b >= q + 1) { amask |= (1u << j); myCnt++; }
            }
        }
        int vv = myCnt;
        #pragma unroll
        for (int o = 1; o < 32; o <<= 1) {
            int t = __shfl_up_sync(0xFFFFFFFFu, vv, o);
            if (lane >= o) vv += t;
        }
        if (lane == 31) wsum[wid] = vv;
        __syncthreads();
        if (wid == 0) {
            int w = wsum[lane];
            #pragma unroll
            for (int o = 1; o < 32; o <<= 1) {
                int t = __shfl_up_sync(0xFFFFFFFFu, w, o);
                if (lane >= o) w += t;
            }
            wsum[lane] = w;
        }
        __syncthreads();
        int jbase = (vv - myCnt) + ((wid > 0) ? wsum[wid - 1] : 0);
        if (tid == 0) sh_A = wsum[(nthr >> 5) - 1];
        #pragma unroll
        for (int j = 0; j < 16; ++j) {
            if (amask & (1u << j)) {
                int q = q0 + j;
                g_bdata[jbase++] = ((u32)rs[j] << 14) | (u32)g_si[q];
            }
        }
        __syncthreads();
    }
    const int A = sh_A;

    for (int i = tid; i < PMAX; i += nthr) wr[i] = (i < P) ? g_writer[i] : (u16)0xFFFFu;
    __syncthreads();

    if (A > 0) {
        const int UN = P + A;

        // add accepted ranks to the pool histogram (g_hist preserved)
        for (int j = tid; j < A; j += nthr) atomicAdd(&g_hist[g_bdata[j] >> 14], 1u);
        __syncthreads();
        {   // exclusive prefix over RMAX -> g_cursor (U cursors)
            const int CPT = RMAX / 1024;
            const int base = tid * CPT;
            u32 s = 0;
            #pragma unroll
            for (int j = 0; j < CPT; ++j) s += g_hist[base + j];
            u32 vv = s;
            #pragma unroll
            for (int o = 1; o < 32; o <<= 1) {
                u32 t = __shfl_up_sync(0xFFFFFFFFu, vv, o);
                if (lane >= o) vv += t;
            }
            if (lane == 31) wsum[wid] = (int)vv;
            __syncthreads();
            if (wid == 0) {
                u32 w = (u32)wsum[lane];
                #pragma unroll
                for (int o = 1; o < 32; o <<= 1) {
                    u32 t = __shfl_up_sync(0xFFFFFFFFu, w, o);
                    if (lane >= o) w += t;
                }
                wsum[lane] = (int)w;
            }
            __syncthreads();
            u32 run = (vv - s) + ((wid > 0) ? (u32)wsum[wid - 1] : 0u);
            #pragma unroll
            for (int j = 0; j < CPT; ++j) {
                u32 h = g_hist[base + j];
                g_cursor[base + j] = run;
                run += h;
            }
            __syncthreads();
        }
        // scatter: elem = rank<<17 | type<<16 | id
        for (int i = tid; i < P; i += nthr) {
            u32 r = (u32)g_psr[i];
            u32 pos = atomicAdd(&g_cursor[r], 1u);
            gU[pos] = (r << 17) | (u32)i;
        }
        for (int j = tid; j < A; j += nthr) {
            u32 r = g_bdata[j] >> 14;
            u32 pos = atomicAdd(&g_cursor[r], 1u);
            gU[pos] = (r << 17) | 0x10000u | (u32)j;
        }
        __syncthreads();

        // tie detection
        if (tid == 0) sh_anyTies = 0;
        __syncthreads();
        for (int p = tid; p + 1 < UN; p += nthr)
            if ((gU[p] >> 17) == (gU[p + 1] >> 17)) sh_anyTies = 1;
        __syncthreads();

        const int MAXIT = 32;
        for (int it = 0; it < MAXIT; ++it) {
            for (int j = tid; j < A; j += nthr) {
                u32 e = gU[j];
                par[j] = (e & 0x10000u) ? (e & 0xFFFFu) : (0x80000000u | (e & 0xFFFFu));
            }
            __syncthreads();
            for (int rd = 0; rd < 15; ++rd) {
                if (tid == 0) sh_changed = 0;
                __syncthreads();
                for (int j = tid; j < A; j += nthr) {
                    u32 pv = par[j];
                    if (!(pv & 0x80000000u)) {
                        u32 g = par[pv];
                        par[j] = g;
                        if (!(g & 0x80000000u)) sh_changed = 1;
                    }
                }
                __syncthreads();
                if (!sh_changed) break;
            }
            if (!sh_anyTies) break;
            if (it == MAXIT - 1) break;
            if (tid == 0) sh_changed = 0;
            __syncthreads();
            for (int p = tid; p < UN; p += nthr) {
                u32 r = gU[p] >> 17;
                bool leader = (p == 0) || ((gU[p - 1] >> 17) != r);
                if (leader && p + 1 < UN && (gU[p + 1] >> 17) == r) {
                    int len = 1;
                    while (p + len < UN && (gU[p + len] >> 17) == r) len++;
                    bool ch = false;
                    for (int a = 1; a < len; ++a) {
                        u32 x = gU[p + a];
                        u32 sx = (x & 0x10000u) ? (par[x & 0xFFFFu] & 0xFFFFu) : (x & 0xFFFFu);
                        u32 kx = (sx << 1) | ((x >> 16) & 1u);
                        int b = a;
                        while (b > 0) {
                            u32 y = gU[p + b - 1];
                            u32 sy = (y & 0x10000u) ? (par[y & 0xFFFFu] & 0xFFFFu) : (y & 0xFFFFu);
                            u32 ky = (sy << 1) | ((y >> 16) & 1u);
                            if (ky <= kx) break;
                            gU[p + b] = y; b--; ch = true;
                        }
                        gU[p + b] = x;
                    }
                    if (ch) sh_changed = 1;
                }
            }
            __syncthreads();
            if (!sh_changed) break;
        }

        // survivors (positions >= A) write the final map
        for (int pos = A + tid; pos < UN; pos += nthr) {
            u32 e = gU[pos];
            if (e & 0x10000u) {
                u32 j = e & 0xFFFFu;
                u32 s = par[j] & 0xFFFFu;
                if (s < (u32)P) wr[s] = (u16)(g_bdata[j] & 0x3FFFu);
            }
        }
        __syncthreads();
    }

    // epilogue
    const long long obase = (long long)P * (long long)D;
    for (int i = tid; i < P; i += nthr) {
        u16 w = wr[i];
        g_writer[i] = w;
        if (obase + i < out_size)
            out[obase + i] = (w != 0xFFFFu) ? scores[w] : priorities[i];
    }
    if (tid == 0 && obase + P < out_size)
        out[obase + P] = (float)g_fc;

    // restore the g_hist == 0 invariant for the next graph replay
    for (int i = tid; i < RMAX; i += nthr) g_hist[i] = 0u;
}

// ---------------------------------------------------------------------------
// Row gather: one block per pool slot.
// ---------------------------------------------------------------------------
__global__ void k_copy(const float* __restrict__ pool,
                       const float* __restrict__ summaries,
                       float* __restrict__ out, int D) {
    const int row = blockIdx.x;
    const u16 w = g_writer[row];
    const float* src = (w == 0xFFFFu) ? (pool + (long long)row * D)
                                      : (summaries + (long long)w * D);
    float* dst = out + (long long)row * D;
    if ((D & 3) == 0) {
        const float4* s4 = (const float4*)src;
        float4* d4 = (float4*)dst;
        for (int i = threadIdx.x; i < (D >> 2); i += blockDim.x) d4[i] = s4[i];
    } else {
        for (int i = threadIdx.x; i < D; i += blockDim.x) dst[i] = src[i];
    }
}

// ---------------------------------------------------------------------------
// Inputs (metadata order): summaries[N,D] f32, scores[N] f32, pool[P,D] f32,
// priorities[P] f32, count i32 scalar.
// Output: concat(pool_out[P*D], priorities[P], count) as f32.
// ---------------------------------------------------------------------------
extern "C" void kernel_launch(void* const* d_in, const int* in_sizes, int n_in,
                              void* d_out, int out_size) {
    const float* summaries  = (const float*)d_in[0];
    const float* scores     = (const float*)d_in[1];
    const float* pool       = (const float*)d_in[2];
    const float* priorities = (const float*)d_in[3];
    const int*   countp     = (const int*)d_in[4];

    const int N = in_sizes[1];
    const int P = in_sizes[3];
    const int D = (N > 0) ? (in_sizes[0] / N) : 0;
    const int M = N + P;
    float* out = (float*)d_out;

    const int cls_smem = NMAX * 4 + PMAX * 2;            // 73,728
    const int res_smem = (RMAX + NMAX) * 4 + PMAX * 2;   // 155,648
    cudaFuncSetAttribute(k_classify, cudaFuncAttributeMaxDynamicSharedMemorySize, cls_smem);
    cudaFuncSetAttribute(k_resolve,  cudaFuncAttributeMaxDynamicSharedMemorySize, res_smem);

    k_hist     <<<(M + 255) / 256, 256>>>(scores, priorities, N, P);
    k_scan     <<<1, 1024>>>();
    k_scatter  <<<(M + 255) / 256, 256>>>(scores, priorities, N, P);
    k_rank     <<<(M + 255) / 256, 256>>>(scores, priorities, N, P);
    k_classify <<<1, 1024, cls_smem>>>(scores, countp, N, P);
    k_chunksort<<<NMAX / 256, 256>>>();
    k_count    <<<512, 256>>>();
    k_resolve  <<<1, 1024, res_smem>>>(scores, priorities, out, P, D, (long long)out_size);
    k_copy     <<<P, 256>>>(pool, summaries, out, D);
}